// round 10
// baseline (speedup 1.0000x reference)
#include <cuda_runtime.h>
#include <cuda_fp16.h>
#include <cstdint>

#define NN   4096
#define BB   16
#define NB   256      // nodes per batch
#define ND   9        // NUM_DEG
#define FF   128
#define MCH  1152     // 9*128
#define NFREQ 64
#define SZSLAB (BB * NB * NB)

// ---------------- scratch (static device memory; no allocations) ------------
__device__ float g_q[NN * MCH];
__device__ float g_k[NN * MCH];
__device__ float g_v[NN * MCH];
__device__ float g_cosT[3 * NFREQ * NN];   // [axis][f][node]
__device__ float g_sinT[3 * NFREQ * NN];   // [axis][f][node]
__device__ float g_Spart[9u * SZSLAB];     // 9 partial slabs
__device__ float g_S[SZSLAB];

// ---------------- helpers ------------------------------------------------------
__device__ __forceinline__ uint32_t cvsm(const void* p) {
    return (uint32_t)__cvta_generic_to_shared(p);
}
__device__ __forceinline__ void ldsm4(uint32_t* r, uint32_t addr) {
    asm volatile("ldmatrix.sync.aligned.m8n8.x4.shared.b16 {%0,%1,%2,%3}, [%4];"
                 : "=r"(r[0]), "=r"(r[1]), "=r"(r[2]), "=r"(r[3])
                 : "r"(addr));
}
__device__ __forceinline__ void mma16816h(float* d, const uint32_t* a,
                                          uint32_t b0, uint32_t b1) {
    asm volatile(
        "mma.sync.aligned.m16n8k16.row.col.f32.f16.f16.f32 "
        "{%0,%1,%2,%3}, {%4,%5,%6,%7}, {%8,%9}, {%0,%1,%2,%3};"
        : "+f"(d[0]), "+f"(d[1]), "+f"(d[2]), "+f"(d[3])
        : "r"(a[0]), "r"(a[1]), "r"(a[2]), "r"(a[3]), "r"(b0), "r"(b1));
}

// ---- fp16 single-term mma over staged chunk: A at base, B at base+ARR ----
template <int PITCH, int NK16>
__device__ __forceinline__ void mma_chunk_h(
    const __half* base, float acc[2][8][4],
    int wm, int wn, int at_r, int at_k, int bt_n, int bt_k) {
    const int ARR = 128 * PITCH;
    const __half* A = base;
    const __half* B = base + ARR;
#pragma unroll
    for (int k16 = 0; k16 < NK16; k16++) {
        int kc = k16 * 16 + at_k;
        uint32_t ah[2][4];
#pragma unroll
        for (int mt = 0; mt < 2; mt++) {
            int row = wm * 32 + mt * 16 + at_r;
            ldsm4(ah[mt], cvsm(A + row * PITCH + kc));
        }
        int kcb = k16 * 16 + bt_k;
#pragma unroll
        for (int np = 0; np < 4; np++) {
            int n = wn * 64 + np * 16 + bt_n;
            uint32_t bb[4];
            ldsm4(bb, cvsm(B + n * PITCH + kcb));
#pragma unroll
            for (int mt = 0; mt < 2; mt++) {
#pragma unroll
                for (int nt = 0; nt < 2; nt++) {
                    mma16816h(acc[mt][np * 2 + nt], ah[mt],
                              bb[nt * 2], bb[nt * 2 + 1]);
                }
            }
        }
    }
}

#define SPITCH 40
#define SARR   (128 * SPITCH)
#define PO_SMEM (2 * 2 * SARR * 2)   // 2 stages x (A+B) x fp16 = 40960 B

// ---------------- kernel: cos/sin tables (transposed [a][f][node]) ------------
__global__ void k_cs(const float* __restrict__ pos) {
    int idx = blockIdx.x * 256 + threadIdx.x;
    if (idx >= NN * 3 * NFREQ) return;
    int n = idx & (NN - 1);
    int rest = idx >> 12;
    int c = rest & 63;
    int a = rest >> 6;
    float theta = (8.0f / (63.0f * 10.0f)) * (float)c;
    float ph = pos[n * 3 + a] * theta;
    float s, co;
    sincosf(ph, &s, &co);
    g_cosT[idx] = co;   // idx == (a*64+c)*4096 + n
    g_sinT[idx] = s;
}

// ---------------- kernel: q/k/v projections via fp16 mma.sync ------------------
__global__ void __launch_bounds__(256, 2)
k_proj(const float* __restrict__ X,
       const float* __restrict__ Wq, const float* __restrict__ bq,
       const float* __restrict__ Wk, const float* __restrict__ bk,
       const float* __restrict__ Wv, const float* __restrict__ bv) {
    extern __shared__ unsigned char smraw[];
    __half* smh = (__half*)smraw;

    int z = blockIdx.z;
    int p = z / 3, l = z % 3;
    const int cnt = (l == 0) ? 1 : (l == 1 ? 3 : 5);
    const int m0  = (l == 0) ? 0 : (l == 1 ? 1 : 4);
    int ntiles = (NN * cnt) >> 7;
    if ((int)blockIdx.x >= ntiles) return;

    const float* W    = (p == 0 ? Wq : (p == 1 ? Wk : Wv)) + l * FF * FF;
    const float* bias = (p == 0 ? bq : (p == 1 ? bk : bv));
    float* dst = (p == 0 ? g_q : (p == 1 ? g_k : g_v));

    int row0 = blockIdx.x * 128;
    int tid = threadIdx.x;
    int wid = tid >> 5, lane = tid & 31;
    int wm = wid & 3, wn = wid >> 2;
    int kq = tid & 7, rr = tid >> 3;
    int kk = tid & 31, ng = tid >> 5;

    const float* arow[4];
#pragma unroll
    for (int i = 0; i < 4; i++) {
        int rg = row0 + rr + i * 32;
        int node = rg / cnt, mi = rg - node * cnt;
        arow[i] = X + ((size_t)node * ND + (m0 + mi)) * FF;
    }

    float acc[2][8][4];
#pragma unroll
    for (int mt = 0; mt < 2; mt++)
#pragma unroll
        for (int nt = 0; nt < 8; nt++)
#pragma unroll
            for (int e = 0; e < 4; e++) acc[mt][nt][e] = 0.0f;

    int at_r = (lane & 7) + ((lane >> 3) & 1) * 8;
    int at_k = (lane >> 4) * 8;
    int bt_n = (lane & 7) + ((lane & 16) ? 8 : 0);
    int bt_k = ((lane >> 3) & 1) * 8;

    auto stage = [&](int c, int st) {
        int f0 = c * 32;
        __half* Ah = smh + st * 2 * SARR;
#pragma unroll
        for (int i = 0; i < 4; i++) {
            int r = rr + i * 32;
            float4 v = *(const float4*)(arow[i] + f0 + kq * 4);
            union { __half2 h2[2]; uint2 u; } pk;
            pk.h2[0] = __floats2half2_rn(v.x, v.y);
            pk.h2[1] = __floats2half2_rn(v.z, v.w);
            *(uint2*)(Ah + r * SPITCH + kq * 4) = pk.u;
        }
        __half* Bh = Ah + SARR;
#pragma unroll
        for (int j = 0; j < 4; j++) {
            int n0 = ng * 16 + j * 4;
            float4 w = *(const float4*)(W + (size_t)(f0 + kk) * 128 + n0);
            float ws[4] = {w.x, w.y, w.z, w.w};
#pragma unroll
            for (int e = 0; e < 4; e++)
                Bh[(n0 + e) * SPITCH + kk] = __float2half_rn(ws[e]);
        }
    };

    stage(0, 0);
    __syncthreads();
    for (int c = 0; c < 4; c++) {
        int st = c & 1;
        if (c + 1 < 4) stage(c + 1, st ^ 1);
        mma_chunk_h<SPITCH, 2>(smh + st * 2 * SARR, acc, wm, wn, at_r, at_k, bt_n, bt_k);
        __syncthreads();
    }

    int tr = lane >> 2, tc = (lane & 3) * 2;
#pragma unroll
    for (int mt = 0; mt < 2; mt++) {
#pragma unroll
        for (int half = 0; half < 2; half++) {
            int rgl = row0 + wm * 32 + mt * 16 + tr + half * 8;
            int node = rgl / cnt, mi = rgl - node * cnt;
            size_t obase = (size_t)node * MCH + (m0 + mi) * FF;
#pragma unroll
            for (int nt = 0; nt < 8; nt++) {
                int col = wn * 64 + nt * 8 + tc;
                float d0 = acc[mt][nt][half * 2 + 0];
                float d1 = acc[mt][nt][half * 2 + 1];
                if (l == 0) { d0 += bias[col]; d1 += bias[col + 1]; }
                *(float2*)(dst + obase + col) = make_float2(d0, d1);
            }
        }
    }
}

// ---------------- kernel: score partials via fp16 mma.sync --------------------
// Tables read from transposed layout [a][f][node] -> coalesced lane access.
#define KP2 72
#define KA2 (128 * KP2)
#define KS_SMEM (2 * 2 * KA2 * 2)   // 73728 B

__global__ void __launch_bounds__(256, 2)
k_score() {
    extern __shared__ unsigned char smraw[];
    __half* smh = (__half*)smraw;

    int zz = blockIdx.z;
    int b = zz / 9, sp = zz - b * 9;
    int a = sp / 3, mc = sp - a * 3;
    int nb_i = b * NB + blockIdx.x * 128;
    int nb_j = b * NB + blockIdx.y * 128;
    int tid = threadIdx.x;
    int wid = tid >> 5, lane = tid & 31;
    int wm = wid & 3, wn = wid >> 2;
    int kq = tid & 7, rr = tid >> 3;
    int chbase = mc * 384;

    float acc[2][8][4];
#pragma unroll
    for (int mt = 0; mt < 2; mt++)
#pragma unroll
        for (int nt = 0; nt < 8; nt++)
#pragma unroll
            for (int e = 0; e < 4; e++) acc[mt][nt][e] = 0.0f;

    int at_r = (lane & 7) + ((lane >> 3) & 1) * 8;
    int at_k = (lane >> 4) * 8;
    int bt_n = (lane & 7) + ((lane & 16) ? 8 : 0);
    int bt_k = ((lane >> 3) & 1) * 8;

    auto stage = [&](int c, int st) {
        int chl = c * 32 + kq * 4;
        int ch  = chbase + chl;
        int f   = (chl & 127) >> 1;
        const float* tc0 = g_cosT + (a * 64 + f) * NN;
        const float* tc1 = tc0 + NN;
        const float* ts0 = g_sinT + (a * 64 + f) * NN;
        const float* ts1 = ts0 + NN;
#pragma unroll
        for (int pass = 0; pass < 2; pass++) {
            const float* src = pass == 0 ? g_q : g_k;
            int nb = pass == 0 ? nb_i : nb_j;
            __half* D = smh + st * 2 * KA2 + pass * KA2;
#pragma unroll
            for (int i = 0; i < 4; i++) {
                int r = rr + i * 32;
                int node = nb + r;
                float c0 = tc0[node], c1 = tc1[node];
                float s0 = ts0[node], s1 = ts1[node];
                float4 v = *(const float4*)(src + (size_t)node * MCH + ch);
                union { __half2 h2[2]; uint2 u; } p;
                p.h2[0] = __floats2half2_rn(v.x * c0, v.y * c0);
                p.h2[1] = __floats2half2_rn(v.z * c1, v.w * c1);
                *(uint2*)(D + r * KP2 + kq * 4) = p.u;
                p.h2[0] = __floats2half2_rn(v.x * s0, v.y * s0);
                p.h2[1] = __floats2half2_rn(v.z * s1, v.w * s1);
                *(uint2*)(D + r * KP2 + 32 + kq * 4) = p.u;
            }
        }
    };

    auto mma_f16 = [&](int st) {
        mma_chunk_h<KP2, 4>(smh + st * 2 * KA2, acc, wm, wn, at_r, at_k, bt_n, bt_k);
    };

    stage(0, 0);
    __syncthreads();
    for (int c = 0; c < 12; c++) {
        int st = c & 1;
        if (c + 1 < 12) stage(c + 1, st ^ 1);
        mma_f16(st);
        __syncthreads();
    }

    size_t base = ((size_t)sp * BB + b) * (NB * NB);
    int gr = blockIdx.x * 128 + wm * 32;
    int gc = blockIdx.y * 128 + wn * 64;
    int tr = lane >> 2, tc2 = (lane & 3) * 2;
#pragma unroll
    for (int mt = 0; mt < 2; mt++) {
#pragma unroll
        for (int nt = 0; nt < 8; nt++) {
            int r0 = gr + mt * 16 + tr;
            int cc = gc + nt * 8 + tc2;
            float2 d01 = make_float2(acc[mt][nt][0], acc[mt][nt][1]);
            float2 d23 = make_float2(acc[mt][nt][2], acc[mt][nt][3]);
            *(float2*)(g_Spart + base + (size_t)r0 * NB + cc) = d01;
            *(float2*)(g_Spart + base + (size_t)(r0 + 8) * NB + cc) = d23;
        }
    }
}

// ---------------- kernel: slab reduce -----------------------------------------
__global__ void k_reduceS() {
    int i = blockIdx.x * 256 + threadIdx.x;
    if (i >= SZSLAB) return;
    float s = 0.0f;
#pragma unroll
    for (int sl = 0; sl < 9; sl++) s += g_Spart[(size_t)sl * SZSLAB + i];
    g_S[i] = s * (1.0f / 3.0f);   // = 2 * grid_w (pairing factor * 1/6)
}

// ---------------- kernel: out = Sbar @ V (+mask) via fp16 mma.sync -------------
__global__ void __launch_bounds__(256, 2)
k_out(const int* __restrict__ bseg, const int* __restrict__ gmask,
      float* __restrict__ out) {
    extern __shared__ unsigned char smraw[];
    __half* smh = (__half*)smraw;

    int b = blockIdx.z;
    int r0 = blockIdx.x * 128;
    int d0 = blockIdx.y * 128;
    int tid = threadIdx.x;
    int wid = tid >> 5, lane = tid & 31;
    int wm = wid & 3, wn = wid >> 2;
    int kq = tid & 7, rr = tid >> 3;
    int kk = tid & 31, ng = tid >> 5;

    float acc[2][8][4];
#pragma unroll
    for (int mt = 0; mt < 2; mt++)
#pragma unroll
        for (int nt = 0; nt < 8; nt++)
#pragma unroll
            for (int e = 0; e < 4; e++) acc[mt][nt][e] = 0.0f;

    int at_r = (lane & 7) + ((lane >> 3) & 1) * 8;
    int at_k = (lane >> 4) * 8;
    int bt_n = (lane & 7) + ((lane & 16) ? 8 : 0);
    int bt_k = ((lane >> 3) & 1) * 8;

    auto stage = [&](int c, int st) {
        int j0 = c * 32;
        __half* Ah = smh + st * 2 * SARR;
#pragma unroll
        for (int i = 0; i < 4; i++) {
            int r = rr + i * 32;
            float4 v = *(const float4*)(g_S + ((size_t)b * NB + r0 + r) * NB + j0 + kq * 4);
            union { __half2 h2[2]; uint2 u; } pk;
            pk.h2[0] = __floats2half2_rn(v.x, v.y);
            pk.h2[1] = __floats2half2_rn(v.z, v.w);
            *(uint2*)(Ah + r * SPITCH + kq * 4) = pk.u;
        }
        __half* Bh = Ah + SARR;
#pragma unroll
        for (int j = 0; j < 4; j++) {
            int n0 = ng * 16 + j * 4;
            float4 v = *(const float4*)(g_v + ((size_t)(b * NB + j0 + kk)) * MCH + d0 + n0);
            float vs[4] = {v.x, v.y, v.z, v.w};
#pragma unroll
            for (int e = 0; e < 4; e++)
                Bh[(n0 + e) * SPITCH + kk] = __float2half_rn(vs[e]);
        }
    };

    stage(0, 0);
    __syncthreads();
    for (int c = 0; c < 8; c++) {
        int st = c & 1;
        if (c + 1 < 8) stage(c + 1, st ^ 1);
        mma_chunk_h<SPITCH, 2>(smh + st * 2 * SARR, acc, wm, wn, at_r, at_k, bt_n, bt_k);
        __syncthreads();
    }

    int tr = lane >> 2, tc = (lane & 3) * 2;
#pragma unroll
    for (int mt = 0; mt < 2; mt++) {
#pragma unroll
        for (int half = 0; half < 2; half++) {
            int node = b * NB + r0 + wm * 32 + mt * 16 + tr + half * 8;
            bool mk = gmask[bseg[node]] != 0;
#pragma unroll
            for (int nt = 0; nt < 8; nt++) {
                int col = wn * 64 + nt * 8 + tc;
                float o0 = mk ? acc[mt][nt][half * 2 + 0] : 0.0f;
                float o1 = mk ? acc[mt][nt][half * 2 + 1] : 0.0f;
                *(float2*)(out + (size_t)node * MCH + d0 + col) = make_float2(o0, o1);
            }
        }
    }
}

// ---------------- launcher ----------------------------------------------------
extern "C" void kernel_launch(void* const* d_in, const int* in_sizes, int n_in,
                              void* d_out, int out_size) {
    const float* X   = (const float*)d_in[0];
    const float* pos = (const float*)d_in[1];
    const int* bseg  = (const int*)d_in[2];
    const int* gmask = (const int*)d_in[3];   // bool -> int32 in harness
    const float* Wq = (const float*)d_in[4];
    const float* bq = (const float*)d_in[5];
    const float* Wk = (const float*)d_in[6];
    const float* bk = (const float*)d_in[7];
    const float* Wv = (const float*)d_in[8];
    const float* bv = (const float*)d_in[9];
    float* out = (float*)d_out;

    cudaFuncSetAttribute(k_proj,  cudaFuncAttributeMaxDynamicSharedMemorySize, PO_SMEM);
    cudaFuncSetAttribute(k_score, cudaFuncAttributeMaxDynamicSharedMemorySize, KS_SMEM);
    cudaFuncSetAttribute(k_out,   cudaFuncAttributeMaxDynamicSharedMemorySize, PO_SMEM);

    k_cs<<<(NN * 3 * NFREQ + 255) / 256, 256>>>(pos);
    k_proj<<<dim3(160, 1, 9), 256, PO_SMEM>>>(X, Wq, bq, Wk, bk, Wv, bv);
    k_score<<<dim3(2, 2, BB * 9), 256, KS_SMEM>>>();
    k_reduceS<<<(SZSLAB + 255) / 256, 256>>>();
    k_out<<<dim3(2, 9, BB), 256, PO_SMEM>>>(bseg, gmask, out);
}

// round 11
// speedup vs baseline: 1.0689x; 1.0689x over previous
#include <cuda_runtime.h>
#include <cuda_fp16.h>
#include <cstdint>

#define NN   4096
#define BB   16
#define NB   256      // nodes per batch
#define ND   9        // NUM_DEG
#define FF   128
#define MCH  1152     // 9*128
#define NFREQ 64
#define SZSLAB (BB * NB * NB)

// ---------------- scratch (static device memory; no allocations) ------------
__device__ float g_q[NN * MCH];
__device__ float g_k[NN * MCH];
__device__ float g_v[NN * MCH];
__device__ float g_cos[NN * 3 * NFREQ];   // [node][axis][f]
__device__ float g_sin[NN * 3 * NFREQ];
__device__ float g_Spart[9u * SZSLAB];    // 9 partial slabs
__device__ float g_S[SZSLAB];

// ---------------- helpers ------------------------------------------------------
__device__ __forceinline__ uint32_t cvsm(const void* p) {
    return (uint32_t)__cvta_generic_to_shared(p);
}
__device__ __forceinline__ void ldsm4(uint32_t* r, uint32_t addr) {
    asm volatile("ldmatrix.sync.aligned.m8n8.x4.shared.b16 {%0,%1,%2,%3}, [%4];"
                 : "=r"(r[0]), "=r"(r[1]), "=r"(r[2]), "=r"(r[3])
                 : "r"(addr));
}
__device__ __forceinline__ void mma16816h(float* d, const uint32_t* a,
                                          uint32_t b0, uint32_t b1) {
    asm volatile(
        "mma.sync.aligned.m16n8k16.row.col.f32.f16.f16.f32 "
        "{%0,%1,%2,%3}, {%4,%5,%6,%7}, {%8,%9}, {%0,%1,%2,%3};"
        : "+f"(d[0]), "+f"(d[1]), "+f"(d[2]), "+f"(d[3])
        : "r"(a[0]), "r"(a[1]), "r"(a[2]), "r"(a[3]), "r"(b0), "r"(b1));
}

// ---- fp16 single-term mma over staged chunk: A at base, B at base+ARR ----
template <int PITCH, int NK16>
__device__ __forceinline__ void mma_chunk_h(
    const __half* base, float acc[2][8][4],
    int wm, int wn, int at_r, int at_k, int bt_n, int bt_k) {
    const int ARR = 128 * PITCH;
    const __half* A = base;
    const __half* B = base + ARR;
#pragma unroll
    for (int k16 = 0; k16 < NK16; k16++) {
        int kc = k16 * 16 + at_k;
        uint32_t ah[2][4];
#pragma unroll
        for (int mt = 0; mt < 2; mt++) {
            int row = wm * 32 + mt * 16 + at_r;
            ldsm4(ah[mt], cvsm(A + row * PITCH + kc));
        }
        int kcb = k16 * 16 + bt_k;
#pragma unroll
        for (int np = 0; np < 4; np++) {
            int n = wn * 64 + np * 16 + bt_n;
            uint32_t bb[4];
            ldsm4(bb, cvsm(B + n * PITCH + kcb));
#pragma unroll
            for (int mt = 0; mt < 2; mt++) {
#pragma unroll
                for (int nt = 0; nt < 2; nt++) {
                    mma16816h(acc[mt][np * 2 + nt], ah[mt],
                              bb[nt * 2], bb[nt * 2 + 1]);
                }
            }
        }
    }
}

#define SPITCH 40
#define SARR   (128 * SPITCH)
#define PO_SMEM (2 * 2 * SARR * 2)   // 2 stages x (A+B) x fp16 = 40960 B

// ---------------- kernel: cos/sin tables ([node][axis][f]) --------------------
__global__ void k_cs(const float* __restrict__ pos) {
    int idx = blockIdx.x * 256 + threadIdx.x;
    if (idx >= NN * 3 * NFREQ) return;
    int c = idx & 63;
    int a = (idx >> 6) % 3;
    int n = idx / 192;
    float theta = (8.0f / (63.0f * 10.0f)) * (float)c;
    float ph = pos[n * 3 + a] * theta;
    float s, co;
    sincosf(ph, &s, &co);
    g_cos[idx] = co;
    g_sin[idx] = s;
}

// ---------------- kernel: q/k/v projections via fp16 mma.sync ------------------
__global__ void __launch_bounds__(256, 2)
k_proj(const float* __restrict__ X,
       const float* __restrict__ Wq, const float* __restrict__ bq,
       const float* __restrict__ Wk, const float* __restrict__ bk,
       const float* __restrict__ Wv, const float* __restrict__ bv) {
    extern __shared__ unsigned char smraw[];
    __half* smh = (__half*)smraw;

    int z = blockIdx.z;
    int p = z / 3, l = z % 3;
    const int cnt = (l == 0) ? 1 : (l == 1 ? 3 : 5);
    const int m0  = (l == 0) ? 0 : (l == 1 ? 1 : 4);
    int ntiles = (NN * cnt) >> 7;
    if ((int)blockIdx.x >= ntiles) return;

    const float* W    = (p == 0 ? Wq : (p == 1 ? Wk : Wv)) + l * FF * FF;
    const float* bias = (p == 0 ? bq : (p == 1 ? bk : bv));
    float* dst = (p == 0 ? g_q : (p == 1 ? g_k : g_v));

    int row0 = blockIdx.x * 128;
    int tid = threadIdx.x;
    int wid = tid >> 5, lane = tid & 31;
    int wm = wid & 3, wn = wid >> 2;
    int kq = tid & 7, rr = tid >> 3;
    int kk = tid & 31, ng = tid >> 5;

    const float* arow[4];
#pragma unroll
    for (int i = 0; i < 4; i++) {
        int rg = row0 + rr + i * 32;
        int node = rg / cnt, mi = rg - node * cnt;
        arow[i] = X + ((size_t)node * ND + (m0 + mi)) * FF;
    }

    float acc[2][8][4];
#pragma unroll
    for (int mt = 0; mt < 2; mt++)
#pragma unroll
        for (int nt = 0; nt < 8; nt++)
#pragma unroll
            for (int e = 0; e < 4; e++) acc[mt][nt][e] = 0.0f;

    int at_r = (lane & 7) + ((lane >> 3) & 1) * 8;
    int at_k = (lane >> 4) * 8;
    int bt_n = (lane & 7) + ((lane & 16) ? 8 : 0);
    int bt_k = ((lane >> 3) & 1) * 8;

    auto stage = [&](int c, int st) {
        int f0 = c * 32;
        __half* Ah = smh + st * 2 * SARR;
#pragma unroll
        for (int i = 0; i < 4; i++) {
            int r = rr + i * 32;
            float4 v = *(const float4*)(arow[i] + f0 + kq * 4);
            union { __half2 h2[2]; uint2 u; } pk;
            pk.h2[0] = __floats2half2_rn(v.x, v.y);
            pk.h2[1] = __floats2half2_rn(v.z, v.w);
            *(uint2*)(Ah + r * SPITCH + kq * 4) = pk.u;
        }
        __half* Bh = Ah + SARR;
#pragma unroll
        for (int j = 0; j < 4; j++) {
            int n0 = ng * 16 + j * 4;
            float4 w = *(const float4*)(W + (size_t)(f0 + kk) * 128 + n0);
            float ws[4] = {w.x, w.y, w.z, w.w};
#pragma unroll
            for (int e = 0; e < 4; e++)
                Bh[(n0 + e) * SPITCH + kk] = __float2half_rn(ws[e]);
        }
    };

    stage(0, 0);
    __syncthreads();
    for (int c = 0; c < 4; c++) {
        int st = c & 1;
        if (c + 1 < 4) stage(c + 1, st ^ 1);
        mma_chunk_h<SPITCH, 2>(smh + st * 2 * SARR, acc, wm, wn, at_r, at_k, bt_n, bt_k);
        __syncthreads();
    }

    int tr = lane >> 2, tc = (lane & 3) * 2;
#pragma unroll
    for (int mt = 0; mt < 2; mt++) {
#pragma unroll
        for (int half = 0; half < 2; half++) {
            int rgl = row0 + wm * 32 + mt * 16 + tr + half * 8;
            int node = rgl / cnt, mi = rgl - node * cnt;
            size_t obase = (size_t)node * MCH + (m0 + mi) * FF;
#pragma unroll
            for (int nt = 0; nt < 8; nt++) {
                int col = wn * 64 + nt * 8 + tc;
                float d0 = acc[mt][nt][half * 2 + 0];
                float d1 = acc[mt][nt][half * 2 + 1];
                if (l == 0) { d0 += bias[col]; d1 += bias[col + 1]; }
                *(float2*)(dst + obase + col) = make_float2(d0, d1);
            }
        }
    }
}

// ---------------- kernel: score partials via fp16 mma.sync, 3-stage pipeline --
#define KP2 72
#define KA2 (128 * KP2)
#define KS_SMEM (3 * 2 * KA2 * 2)   // 3 buffers x (A+B) x fp16 = 110592 B

__global__ void __launch_bounds__(256, 2)
k_score() {
    extern __shared__ unsigned char smraw[];
    __half* smh = (__half*)smraw;

    int zz = blockIdx.z;
    int b = zz / 9, sp = zz - b * 9;
    int a = sp / 3, mc = sp - a * 3;
    int nb_i = b * NB + blockIdx.x * 128;
    int nb_j = b * NB + blockIdx.y * 128;
    int tid = threadIdx.x;
    int wid = tid >> 5, lane = tid & 31;
    int wm = wid & 3, wn = wid >> 2;
    int kq = tid & 7, rr = tid >> 3;
    int chbase = mc * 384;

    float acc[2][8][4];
#pragma unroll
    for (int mt = 0; mt < 2; mt++)
#pragma unroll
        for (int nt = 0; nt < 8; nt++)
#pragma unroll
            for (int e = 0; e < 4; e++) acc[mt][nt][e] = 0.0f;

    int at_r = (lane & 7) + ((lane >> 3) & 1) * 8;
    int at_k = (lane >> 4) * 8;
    int bt_n = (lane & 7) + ((lane & 16) ? 8 : 0);
    int bt_k = ((lane >> 3) & 1) * 8;

    auto stage = [&](int c, int buf) {
        int chl = c * 32 + kq * 4;
        int ch  = chbase + chl;
        int f   = (chl & 127) >> 1;
#pragma unroll
        for (int pass = 0; pass < 2; pass++) {
            const float* src = pass == 0 ? g_q : g_k;
            int nb = pass == 0 ? nb_i : nb_j;
            __half* D = smh + buf * 2 * KA2 + pass * KA2;
#pragma unroll
            for (int i = 0; i < 4; i++) {
                int r = rr + i * 32;
                int node = nb + r;
                const float* tc = g_cos + node * 192 + a * 64 + f;
                const float* ts = g_sin + node * 192 + a * 64 + f;
                float c0 = tc[0], c1 = tc[1];
                float s0 = ts[0], s1 = ts[1];
                float4 v = *(const float4*)(src + (size_t)node * MCH + ch);
                union { __half2 h2[2]; uint2 u; } p;
                p.h2[0] = __floats2half2_rn(v.x * c0, v.y * c0);
                p.h2[1] = __floats2half2_rn(v.z * c1, v.w * c1);
                *(uint2*)(D + r * KP2 + kq * 4) = p.u;
                p.h2[0] = __floats2half2_rn(v.x * s0, v.y * s0);
                p.h2[1] = __floats2half2_rn(v.z * s1, v.w * s1);
                *(uint2*)(D + r * KP2 + 32 + kq * 4) = p.u;
            }
        }
    };

    // 3-stage pipeline: staged data is consumed two mma-phases later.
    stage(0, 0);
    stage(1, 1);
    __syncthreads();
    for (int c = 0; c < 12; c++) {
        if (c + 2 < 12) stage(c + 2, (c + 2) % 3);
        mma_chunk_h<KP2, 4>(smh + (c % 3) * 2 * KA2, acc, wm, wn, at_r, at_k, bt_n, bt_k);
        __syncthreads();
    }

    size_t base = ((size_t)sp * BB + b) * (NB * NB);
    int gr = blockIdx.x * 128 + wm * 32;
    int gc = blockIdx.y * 128 + wn * 64;
    int tr = lane >> 2, tc2 = (lane & 3) * 2;
#pragma unroll
    for (int mt = 0; mt < 2; mt++) {
#pragma unroll
        for (int nt = 0; nt < 8; nt++) {
            int r0 = gr + mt * 16 + tr;
            int cc = gc + nt * 8 + tc2;
            float2 d01 = make_float2(acc[mt][nt][0], acc[mt][nt][1]);
            float2 d23 = make_float2(acc[mt][nt][2], acc[mt][nt][3]);
            *(float2*)(g_Spart + base + (size_t)r0 * NB + cc) = d01;
            *(float2*)(g_Spart + base + (size_t)(r0 + 8) * NB + cc) = d23;
        }
    }
}

// ---------------- kernel: slab reduce (float4) ---------------------------------
__global__ void k_reduceS() {
    int i = (blockIdx.x * 256 + threadIdx.x) * 4;
    if (i >= SZSLAB) return;
    float4 s = *(const float4*)(g_Spart + i);
#pragma unroll
    for (int sl = 1; sl < 9; sl++) {
        float4 t = *(const float4*)(g_Spart + (size_t)sl * SZSLAB + i);
        s.x += t.x; s.y += t.y; s.z += t.z; s.w += t.w;
    }
    s.x *= (1.0f / 3.0f); s.y *= (1.0f / 3.0f);
    s.z *= (1.0f / 3.0f); s.w *= (1.0f / 3.0f);
    *(float4*)(g_S + i) = s;
}

// ---------------- kernel: out = Sbar @ V (+mask) via fp16 mma.sync -------------
__global__ void __launch_bounds__(256, 2)
k_out(const int* __restrict__ bseg, const int* __restrict__ gmask,
      float* __restrict__ out) {
    extern __shared__ unsigned char smraw[];
    __half* smh = (__half*)smraw;

    int b = blockIdx.z;
    int r0 = blockIdx.x * 128;
    int d0 = blockIdx.y * 128;
    int tid = threadIdx.x;
    int wid = tid >> 5, lane = tid & 31;
    int wm = wid & 3, wn = wid >> 2;
    int kq = tid & 7, rr = tid >> 3;
    int kk = tid & 31, ng = tid >> 5;

    float acc[2][8][4];
#pragma unroll
    for (int mt = 0; mt < 2; mt++)
#pragma unroll
        for (int nt = 0; nt < 8; nt++)
#pragma unroll
            for (int e = 0; e < 4; e++) acc[mt][nt][e] = 0.0f;

    int at_r = (lane & 7) + ((lane >> 3) & 1) * 8;
    int at_k = (lane >> 4) * 8;
    int bt_n = (lane & 7) + ((lane & 16) ? 8 : 0);
    int bt_k = ((lane >> 3) & 1) * 8;

    auto stage = [&](int c, int st) {
        int j0 = c * 32;
        __half* Ah = smh + st * 2 * SARR;
#pragma unroll
        for (int i = 0; i < 4; i++) {
            int r = rr + i * 32;
            float4 v = *(const float4*)(g_S + ((size_t)b * NB + r0 + r) * NB + j0 + kq * 4);
            union { __half2 h2[2]; uint2 u; } pk;
            pk.h2[0] = __floats2half2_rn(v.x, v.y);
            pk.h2[1] = __floats2half2_rn(v.z, v.w);
            *(uint2*)(Ah + r * SPITCH + kq * 4) = pk.u;
        }
        __half* Bh = Ah + SARR;
#pragma unroll
        for (int j = 0; j < 4; j++) {
            int n0 = ng * 16 + j * 4;
            float4 v = *(const float4*)(g_v + ((size_t)(b * NB + j0 + kk)) * MCH + d0 + n0);
            float vs[4] = {v.x, v.y, v.z, v.w};
#pragma unroll
            for (int e = 0; e < 4; e++)
                Bh[(n0 + e) * SPITCH + kk] = __float2half_rn(vs[e]);
        }
    };

    stage(0, 0);
    __syncthreads();
    for (int c = 0; c < 8; c++) {
        int st = c & 1;
        if (c + 1 < 8) stage(c + 1, st ^ 1);
        mma_chunk_h<SPITCH, 2>(smh + st * 2 * SARR, acc, wm, wn, at_r, at_k, bt_n, bt_k);
        __syncthreads();
    }

    int tr = lane >> 2, tc = (lane & 3) * 2;
#pragma unroll
    for (int mt = 0; mt < 2; mt++) {
#pragma unroll
        for (int half = 0; half < 2; half++) {
            int node = b * NB + r0 + wm * 32 + mt * 16 + tr + half * 8;
            bool mk = gmask[bseg[node]] != 0;
#pragma unroll
            for (int nt = 0; nt < 8; nt++) {
                int col = wn * 64 + nt * 8 + tc;
                float o0 = mk ? acc[mt][nt][half * 2 + 0] : 0.0f;
                float o1 = mk ? acc[mt][nt][half * 2 + 1] : 0.0f;
                *(float2*)(out + (size_t)node * MCH + d0 + col) = make_float2(o0, o1);
            }
        }
    }
}

// ---------------- launcher ----------------------------------------------------
extern "C" void kernel_launch(void* const* d_in, const int* in_sizes, int n_in,
                              void* d_out, int out_size) {
    const float* X   = (const float*)d_in[0];
    const float* pos = (const float*)d_in[1];
    const int* bseg  = (const int*)d_in[2];
    const int* gmask = (const int*)d_in[3];   // bool -> int32 in harness
    const float* Wq = (const float*)d_in[4];
    const float* bq = (const float*)d_in[5];
    const float* Wk = (const float*)d_in[6];
    const float* bk = (const float*)d_in[7];
    const float* Wv = (const float*)d_in[8];
    const float* bv = (const float*)d_in[9];
    float* out = (float*)d_out;

    cudaFuncSetAttribute(k_proj,  cudaFuncAttributeMaxDynamicSharedMemorySize, PO_SMEM);
    cudaFuncSetAttribute(k_score, cudaFuncAttributeMaxDynamicSharedMemorySize, KS_SMEM);
    cudaFuncSetAttribute(k_out,   cudaFuncAttributeMaxDynamicSharedMemorySize, PO_SMEM);

    k_cs<<<(NN * 3 * NFREQ + 255) / 256, 256>>>(pos);
    k_proj<<<dim3(160, 1, 9), 256, PO_SMEM>>>(X, Wq, bq, Wk, bk, Wv, bv);
    k_score<<<dim3(2, 2, BB * 9), 256, KS_SMEM>>>();
    k_reduceS<<<SZSLAB / 1024, 256>>>();
    k_out<<<dim3(2, 9, BB), 256, PO_SMEM>>>(bseg, gmask, out);
}

// round 12
// speedup vs baseline: 1.1662x; 1.0910x over previous
#include <cuda_runtime.h>
#include <cuda_fp16.h>
#include <cstdint>

#define NN   4096
#define BB   16
#define NB   256      // nodes per batch
#define ND   9        // NUM_DEG
#define FF   128
#define MCH  1152     // 9*128
#define NFREQ 64
#define SZSLAB (BB * NB * NB)

// ---------------- scratch (static device memory; no allocations) ------------
__device__ __half g_q[NN * MCH];
__device__ __half g_k[NN * MCH];
__device__ __half g_v[NN * MCH];
__device__ float g_cos[NN * 3 * NFREQ];   // [node][axis][f]
__device__ float g_sin[NN * 3 * NFREQ];
__device__ float g_Spart[9u * SZSLAB];    // 9 partial slabs
__device__ float g_S[SZSLAB];

// ---------------- helpers ------------------------------------------------------
__device__ __forceinline__ uint32_t cvsm(const void* p) {
    return (uint32_t)__cvta_generic_to_shared(p);
}
__device__ __forceinline__ void ldsm4(uint32_t* r, uint32_t addr) {
    asm volatile("ldmatrix.sync.aligned.m8n8.x4.shared.b16 {%0,%1,%2,%3}, [%4];"
                 : "=r"(r[0]), "=r"(r[1]), "=r"(r[2]), "=r"(r[3])
                 : "r"(addr));
}
__device__ __forceinline__ void mma16816h(float* d, const uint32_t* a,
                                          uint32_t b0, uint32_t b1) {
    asm volatile(
        "mma.sync.aligned.m16n8k16.row.col.f32.f16.f16.f32 "
        "{%0,%1,%2,%3}, {%4,%5,%6,%7}, {%8,%9}, {%0,%1,%2,%3};"
        : "+f"(d[0]), "+f"(d[1]), "+f"(d[2]), "+f"(d[3])
        : "r"(a[0]), "r"(a[1]), "r"(a[2]), "r"(a[3]), "r"(b0), "r"(b1));
}

// ---- fp16 single-term mma over staged chunk: A at base, B at base+ARR ----
template <int PITCH, int NK16>
__device__ __forceinline__ void mma_chunk_h(
    const __half* base, float acc[2][8][4],
    int wm, int wn, int at_r, int at_k, int bt_n, int bt_k) {
    const int ARR = 128 * PITCH;
    const __half* A = base;
    const __half* B = base + ARR;
#pragma unroll
    for (int k16 = 0; k16 < NK16; k16++) {
        int kc = k16 * 16 + at_k;
        uint32_t ah[2][4];
#pragma unroll
        for (int mt = 0; mt < 2; mt++) {
            int row = wm * 32 + mt * 16 + at_r;
            ldsm4(ah[mt], cvsm(A + row * PITCH + kc));
        }
        int kcb = k16 * 16 + bt_k;
#pragma unroll
        for (int np = 0; np < 4; np++) {
            int n = wn * 64 + np * 16 + bt_n;
            uint32_t bb[4];
            ldsm4(bb, cvsm(B + n * PITCH + kcb));
#pragma unroll
            for (int mt = 0; mt < 2; mt++) {
#pragma unroll
                for (int nt = 0; nt < 2; nt++) {
                    mma16816h(acc[mt][np * 2 + nt], ah[mt],
                              bb[nt * 2], bb[nt * 2 + 1]);
                }
            }
        }
    }
}

#define SPITCH 40
#define SARR   (128 * SPITCH)
#define PO_SMEM (2 * 2 * SARR * 2)   // 2 stages x (A+B) x fp16 = 40960 B

// ---------------- kernel: cos/sin tables ([node][axis][f]) --------------------
__global__ void k_cs(const float* __restrict__ pos) {
    int idx = blockIdx.x * 256 + threadIdx.x;
    if (idx >= NN * 3 * NFREQ) return;
    int c = idx & 63;
    int a = (idx >> 6) % 3;
    int n = idx / 192;
    float theta = (8.0f / (63.0f * 10.0f)) * (float)c;
    float ph = pos[n * 3 + a] * theta;
    float s, co;
    sincosf(ph, &s, &co);
    g_cos[idx] = co;
    g_sin[idx] = s;
}

// ---------------- kernel: q/k/v projections via fp16 mma.sync ------------------
// Output stored as fp16 (same rounding downstream staging applied anyway).
__global__ void __launch_bounds__(256, 2)
k_proj(const float* __restrict__ X,
       const float* __restrict__ Wq, const float* __restrict__ bq,
       const float* __restrict__ Wk, const float* __restrict__ bk,
       const float* __restrict__ Wv, const float* __restrict__ bv) {
    extern __shared__ unsigned char smraw[];
    __half* smh = (__half*)smraw;

    int z = blockIdx.z;
    int p = z / 3, l = z % 3;
    const int cnt = (l == 0) ? 1 : (l == 1 ? 3 : 5);
    const int m0  = (l == 0) ? 0 : (l == 1 ? 1 : 4);
    int ntiles = (NN * cnt) >> 7;
    if ((int)blockIdx.x >= ntiles) return;

    const float* W    = (p == 0 ? Wq : (p == 1 ? Wk : Wv)) + l * FF * FF;
    const float* bias = (p == 0 ? bq : (p == 1 ? bk : bv));
    __half* dst = (p == 0 ? g_q : (p == 1 ? g_k : g_v));

    int row0 = blockIdx.x * 128;
    int tid = threadIdx.x;
    int wid = tid >> 5, lane = tid & 31;
    int wm = wid & 3, wn = wid >> 2;
    int kq = tid & 7, rr = tid >> 3;
    int kk = tid & 31, ng = tid >> 5;

    const float* arow[4];
#pragma unroll
    for (int i = 0; i < 4; i++) {
        int rg = row0 + rr + i * 32;
        int node = rg / cnt, mi = rg - node * cnt;
        arow[i] = X + ((size_t)node * ND + (m0 + mi)) * FF;
    }

    float acc[2][8][4];
#pragma unroll
    for (int mt = 0; mt < 2; mt++)
#pragma unroll
        for (int nt = 0; nt < 8; nt++)
#pragma unroll
            for (int e = 0; e < 4; e++) acc[mt][nt][e] = 0.0f;

    int at_r = (lane & 7) + ((lane >> 3) & 1) * 8;
    int at_k = (lane >> 4) * 8;
    int bt_n = (lane & 7) + ((lane & 16) ? 8 : 0);
    int bt_k = ((lane >> 3) & 1) * 8;

    auto stage = [&](int c, int st) {
        int f0 = c * 32;
        __half* Ah = smh + st * 2 * SARR;
#pragma unroll
        for (int i = 0; i < 4; i++) {
            int r = rr + i * 32;
            float4 v = *(const float4*)(arow[i] + f0 + kq * 4);
            union { __half2 h2[2]; uint2 u; } pk;
            pk.h2[0] = __floats2half2_rn(v.x, v.y);
            pk.h2[1] = __floats2half2_rn(v.z, v.w);
            *(uint2*)(Ah + r * SPITCH + kq * 4) = pk.u;
        }
        __half* Bh = Ah + SARR;
#pragma unroll
        for (int j = 0; j < 4; j++) {
            int n0 = ng * 16 + j * 4;
            float4 w = *(const float4*)(W + (size_t)(f0 + kk) * 128 + n0);
            float ws[4] = {w.x, w.y, w.z, w.w};
#pragma unroll
            for (int e = 0; e < 4; e++)
                Bh[(n0 + e) * SPITCH + kk] = __float2half_rn(ws[e]);
        }
    };

    stage(0, 0);
    __syncthreads();
    for (int c = 0; c < 4; c++) {
        int st = c & 1;
        if (c + 1 < 4) stage(c + 1, st ^ 1);
        mma_chunk_h<SPITCH, 2>(smh + st * 2 * SARR, acc, wm, wn, at_r, at_k, bt_n, bt_k);
        __syncthreads();
    }

    int tr = lane >> 2, tc = (lane & 3) * 2;
#pragma unroll
    for (int mt = 0; mt < 2; mt++) {
#pragma unroll
        for (int half = 0; half < 2; half++) {
            int rgl = row0 + wm * 32 + mt * 16 + tr + half * 8;
            int node = rgl / cnt, mi = rgl - node * cnt;
            size_t obase = (size_t)node * MCH + (m0 + mi) * FF;
#pragma unroll
            for (int nt = 0; nt < 8; nt++) {
                int col = wn * 64 + nt * 8 + tc;
                float d0 = acc[mt][nt][half * 2 + 0];
                float d1 = acc[mt][nt][half * 2 + 1];
                if (l == 0) { d0 += bias[col]; d1 += bias[col + 1]; }
                *(__half2*)(dst + obase + col) = __floats2half2_rn(d0, d1);
            }
        }
    }
}

// ---------------- kernel: score partials via fp16 mma.sync, double-buffered ---
#define KP2 72
#define KA2 (128 * KP2)
#define KS_SMEM (2 * 2 * KA2 * 2)   // 73728 B

__global__ void __launch_bounds__(256, 2)
k_score() {
    extern __shared__ unsigned char smraw[];
    __half* smh = (__half*)smraw;

    int zz = blockIdx.z;
    int b = zz / 9, sp = zz - b * 9;
    int a = sp / 3, mc = sp - a * 3;
    int nb_i = b * NB + blockIdx.x * 128;
    int nb_j = b * NB + blockIdx.y * 128;
    int tid = threadIdx.x;
    int wid = tid >> 5, lane = tid & 31;
    int wm = wid & 3, wn = wid >> 2;
    int kq = tid & 7, rr = tid >> 3;
    int chbase = mc * 384;

    float acc[2][8][4];
#pragma unroll
    for (int mt = 0; mt < 2; mt++)
#pragma unroll
        for (int nt = 0; nt < 8; nt++)
#pragma unroll
            for (int e = 0; e < 4; e++) acc[mt][nt][e] = 0.0f;

    int at_r = (lane & 7) + ((lane >> 3) & 1) * 8;
    int at_k = (lane >> 4) * 8;
    int bt_n = (lane & 7) + ((lane & 16) ? 8 : 0);
    int bt_k = ((lane >> 3) & 1) * 8;

    auto stage = [&](int c, int st) {
        int chl = c * 32 + kq * 4;
        int ch  = chbase + chl;
        int f   = (chl & 127) >> 1;
#pragma unroll
        for (int pass = 0; pass < 2; pass++) {
            const __half* src = pass == 0 ? g_q : g_k;
            int nb = pass == 0 ? nb_i : nb_j;
            __half* D = smh + st * 2 * KA2 + pass * KA2;
#pragma unroll
            for (int i = 0; i < 4; i++) {
                int r = rr + i * 32;
                int node = nb + r;
                const float* tc = g_cos + node * 192 + a * 64 + f;
                const float* ts = g_sin + node * 192 + a * 64 + f;
                float c0 = tc[0], c1 = tc[1];
                float s0 = ts[0], s1 = ts[1];
                union { __half2 h2[2]; uint2 u; } raw;
                raw.u = *(const uint2*)(src + (size_t)node * MCH + ch);
                float2 v01 = __half22float2(raw.h2[0]);
                float2 v23 = __half22float2(raw.h2[1]);
                union { __half2 h2[2]; uint2 u; } p;
                p.h2[0] = __floats2half2_rn(v01.x * c0, v01.y * c0);
                p.h2[1] = __floats2half2_rn(v23.x * c1, v23.y * c1);
                *(uint2*)(D + r * KP2 + kq * 4) = p.u;
                p.h2[0] = __floats2half2_rn(v01.x * s0, v01.y * s0);
                p.h2[1] = __floats2half2_rn(v23.x * s1, v23.y * s1);
                *(uint2*)(D + r * KP2 + 32 + kq * 4) = p.u;
            }
        }
    };

    stage(0, 0);
    __syncthreads();
    for (int c = 0; c < 12; c++) {
        int st = c & 1;
        if (c + 1 < 12) stage(c + 1, st ^ 1);
        mma_chunk_h<KP2, 4>(smh + st * 2 * KA2, acc, wm, wn, at_r, at_k, bt_n, bt_k);
        __syncthreads();
    }

    size_t base = ((size_t)sp * BB + b) * (NB * NB);
    int gr = blockIdx.x * 128 + wm * 32;
    int gc = blockIdx.y * 128 + wn * 64;
    int tr = lane >> 2, tc2 = (lane & 3) * 2;
#pragma unroll
    for (int mt = 0; mt < 2; mt++) {
#pragma unroll
        for (int nt = 0; nt < 8; nt++) {
            int r0 = gr + mt * 16 + tr;
            int cc = gc + nt * 8 + tc2;
            float2 d01 = make_float2(acc[mt][nt][0], acc[mt][nt][1]);
            float2 d23 = make_float2(acc[mt][nt][2], acc[mt][nt][3]);
            *(float2*)(g_Spart + base + (size_t)r0 * NB + cc) = d01;
            *(float2*)(g_Spart + base + (size_t)(r0 + 8) * NB + cc) = d23;
        }
    }
}

// ---------------- kernel: slab reduce (float4) ---------------------------------
__global__ void k_reduceS() {
    int i = (blockIdx.x * 256 + threadIdx.x) * 4;
    if (i >= SZSLAB) return;
    float4 s = *(const float4*)(g_Spart + i);
#pragma unroll
    for (int sl = 1; sl < 9; sl++) {
        float4 t = *(const float4*)(g_Spart + (size_t)sl * SZSLAB + i);
        s.x += t.x; s.y += t.y; s.z += t.z; s.w += t.w;
    }
    s.x *= (1.0f / 3.0f); s.y *= (1.0f / 3.0f);
    s.z *= (1.0f / 3.0f); s.w *= (1.0f / 3.0f);
    *(float4*)(g_S + i) = s;
}

// ---------------- kernel: out = Sbar @ V (+mask) via fp16 mma.sync -------------
__global__ void __launch_bounds__(256, 2)
k_out(const int* __restrict__ bseg, const int* __restrict__ gmask,
      float* __restrict__ out) {
    extern __shared__ unsigned char smraw[];
    __half* smh = (__half*)smraw;

    int b = blockIdx.z;
    int r0 = blockIdx.x * 128;
    int d0 = blockIdx.y * 128;
    int tid = threadIdx.x;
    int wid = tid >> 5, lane = tid & 31;
    int wm = wid & 3, wn = wid >> 2;
    int kq = tid & 7, rr = tid >> 3;
    int kk = tid & 31, ng = tid >> 5;

    float acc[2][8][4];
#pragma unroll
    for (int mt = 0; mt < 2; mt++)
#pragma unroll
        for (int nt = 0; nt < 8; nt++)
#pragma unroll
            for (int e = 0; e < 4; e++) acc[mt][nt][e] = 0.0f;

    int at_r = (lane & 7) + ((lane >> 3) & 1) * 8;
    int at_k = (lane >> 4) * 8;
    int bt_n = (lane & 7) + ((lane & 16) ? 8 : 0);
    int bt_k = ((lane >> 3) & 1) * 8;

    auto stage = [&](int c, int st) {
        int j0 = c * 32;
        __half* Ah = smh + st * 2 * SARR;
#pragma unroll
        for (int i = 0; i < 4; i++) {
            int r = rr + i * 32;
            float4 v = *(const float4*)(g_S + ((size_t)b * NB + r0 + r) * NB + j0 + kq * 4);
            union { __half2 h2[2]; uint2 u; } pk;
            pk.h2[0] = __floats2half2_rn(v.x, v.y);
            pk.h2[1] = __floats2half2_rn(v.z, v.w);
            *(uint2*)(Ah + r * SPITCH + kq * 4) = pk.u;
        }
        __half* Bh = Ah + SARR;
#pragma unroll
        for (int j = 0; j < 4; j++) {
            int n0 = ng * 16 + j * 4;
            union { __half h[4]; uint2 u; } raw;
            raw.u = *(const uint2*)(g_v + ((size_t)(b * NB + j0 + kk)) * MCH + d0 + n0);
#pragma unroll
            for (int e = 0; e < 4; e++)
                Bh[(n0 + e) * SPITCH + kk] = raw.h[e];
        }
    };

    stage(0, 0);
    __syncthreads();
    for (int c = 0; c < 8; c++) {
        int st = c & 1;
        if (c + 1 < 8) stage(c + 1, st ^ 1);
        mma_chunk_h<SPITCH, 2>(smh + st * 2 * SARR, acc, wm, wn, at_r, at_k, bt_n, bt_k);
        __syncthreads();
    }

    int tr = lane >> 2, tc = (lane & 3) * 2;
#pragma unroll
    for (int mt = 0; mt < 2; mt++) {
#pragma unroll
        for (int half = 0; half < 2; half++) {
            int node = b * NB + r0 + wm * 32 + mt * 16 + tr + half * 8;
            bool mk = gmask[bseg[node]] != 0;
#pragma unroll
            for (int nt = 0; nt < 8; nt++) {
                int col = wn * 64 + nt * 8 + tc;
                float o0 = mk ? acc[mt][nt][half * 2 + 0] : 0.0f;
                float o1 = mk ? acc[mt][nt][half * 2 + 1] : 0.0f;
                *(float2*)(out + (size_t)node * MCH + d0 + col) = make_float2(o0, o1);
            }
        }
    }
}

// ---------------- launcher ----------------------------------------------------
extern "C" void kernel_launch(void* const* d_in, const int* in_sizes, int n_in,
                              void* d_out, int out_size) {
    const float* X   = (const float*)d_in[0];
    const float* pos = (const float*)d_in[1];
    const int* bseg  = (const int*)d_in[2];
    const int* gmask = (const int*)d_in[3];   // bool -> int32 in harness
    const float* Wq = (const float*)d_in[4];
    const float* bq = (const float*)d_in[5];
    const float* Wk = (const float*)d_in[6];
    const float* bk = (const float*)d_in[7];
    const float* Wv = (const float*)d_in[8];
    const float* bv = (const float*)d_in[9];
    float* out = (float*)d_out;

    cudaFuncSetAttribute(k_proj,  cudaFuncAttributeMaxDynamicSharedMemorySize, PO_SMEM);
    cudaFuncSetAttribute(k_score, cudaFuncAttributeMaxDynamicSharedMemorySize, KS_SMEM);
    cudaFuncSetAttribute(k_out,   cudaFuncAttributeMaxDynamicSharedMemorySize, PO_SMEM);

    k_cs<<<(NN * 3 * NFREQ + 255) / 256, 256>>>(pos);
    k_proj<<<dim3(160, 1, 9), 256, PO_SMEM>>>(X, Wq, bq, Wk, bk, Wv, bv);
    k_score<<<dim3(2, 2, BB * 9), 256, KS_SMEM>>>();
    k_reduceS<<<SZSLAB / 1024, 256>>>();
    k_out<<<dim3(2, 9, BB), 256, PO_SMEM>>>(bseg, gmask, out);
}

// round 13
// speedup vs baseline: 1.2020x; 1.0307x over previous
#include <cuda_runtime.h>
#include <cuda_fp16.h>
#include <cstdint>

#define NN   4096
#define BB   16
#define NB   256      // nodes per batch
#define ND   9        // NUM_DEG
#define FF   128
#define MCH  1152     // 9*128
#define NFREQ 64
#define SZSLAB (BB * NB * NB)

// ---------------- scratch (static device memory; no allocations) ------------
__device__ __half g_q[NN * MCH];
__device__ __half g_k[NN * MCH];
__device__ __half g_v[NN * MCH];
__device__ float g_cos[NN * 3 * NFREQ];   // [node][axis][f]
__device__ float g_sin[NN * 3 * NFREQ];
__device__ float g_Spart[9u * SZSLAB];    // 9 partial slabs
__device__ float g_S[SZSLAB];

// ---------------- helpers ------------------------------------------------------
__device__ __forceinline__ uint32_t cvsm(const void* p) {
    return (uint32_t)__cvta_generic_to_shared(p);
}
__device__ __forceinline__ void ldsm4(uint32_t* r, uint32_t addr) {
    asm volatile("ldmatrix.sync.aligned.m8n8.x4.shared.b16 {%0,%1,%2,%3}, [%4];"
                 : "=r"(r[0]), "=r"(r[1]), "=r"(r[2]), "=r"(r[3])
                 : "r"(addr));
}
__device__ __forceinline__ void mma16816h(float* d, const uint32_t* a,
                                          uint32_t b0, uint32_t b1) {
    asm volatile(
        "mma.sync.aligned.m16n8k16.row.col.f32.f16.f16.f32 "
        "{%0,%1,%2,%3}, {%4,%5,%6,%7}, {%8,%9}, {%0,%1,%2,%3};"
        : "+f"(d[0]), "+f"(d[1]), "+f"(d[2]), "+f"(d[3])
        : "r"(a[0]), "r"(a[1]), "r"(a[2]), "r"(a[3]), "r"(b0), "r"(b1));
}

// ---- fp16 single-term mma over staged chunk: A at base, B at base+ARR ----
template <int PITCH, int NK16>
__device__ __forceinline__ void mma_chunk_h(
    const __half* base, float acc[2][8][4],
    int wm, int wn, int at_r, int at_k, int bt_n, int bt_k) {
    const int ARR = 128 * PITCH;
    const __half* A = base;
    const __half* B = base + ARR;
#pragma unroll
    for (int k16 = 0; k16 < NK16; k16++) {
        int kc = k16 * 16 + at_k;
        uint32_t ah[2][4];
#pragma unroll
        for (int mt = 0; mt < 2; mt++) {
            int row = wm * 32 + mt * 16 + at_r;
            ldsm4(ah[mt], cvsm(A + row * PITCH + kc));
        }
        int kcb = k16 * 16 + bt_k;
#pragma unroll
        for (int np = 0; np < 4; np++) {
            int n = wn * 64 + np * 16 + bt_n;
            uint32_t bb[4];
            ldsm4(bb, cvsm(B + n * PITCH + kcb));
#pragma unroll
            for (int mt = 0; mt < 2; mt++) {
#pragma unroll
                for (int nt = 0; nt < 2; nt++) {
                    mma16816h(acc[mt][np * 2 + nt], ah[mt],
                              bb[nt * 2], bb[nt * 2 + 1]);
                }
            }
        }
    }
}

#define SPITCH 40
#define SARR   (128 * SPITCH)
#define PO_SMEM (2 * 2 * SARR * 2)   // 2 stages x (A+B) x fp16 = 40960 B

// ---------------- kernel: cos/sin tables ([node][axis][f]) --------------------
__global__ void k_cs(const float* __restrict__ pos) {
    int idx = blockIdx.x * 256 + threadIdx.x;
    if (idx >= NN * 3 * NFREQ) return;
    int c = idx & 63;
    int a = (idx >> 6) % 3;
    int n = idx / 192;
    float theta = (8.0f / (63.0f * 10.0f)) * (float)c;
    float ph = pos[n * 3 + a] * theta;
    float s, co;
    sincosf(ph, &s, &co);
    g_cos[idx] = co;
    g_sin[idx] = s;
}

// ---------------- kernel: q/k/v projections via fp16 mma.sync ------------------
__global__ void __launch_bounds__(256, 2)
k_proj(const float* __restrict__ X,
       const float* __restrict__ Wq, const float* __restrict__ bq,
       const float* __restrict__ Wk, const float* __restrict__ bk,
       const float* __restrict__ Wv, const float* __restrict__ bv) {
    extern __shared__ unsigned char smraw[];
    __half* smh = (__half*)smraw;

    int z = blockIdx.z;
    int p = z / 3, l = z % 3;
    const int cnt = (l == 0) ? 1 : (l == 1 ? 3 : 5);
    const int m0  = (l == 0) ? 0 : (l == 1 ? 1 : 4);
    int ntiles = (NN * cnt) >> 7;
    if ((int)blockIdx.x >= ntiles) return;

    const float* W    = (p == 0 ? Wq : (p == 1 ? Wk : Wv)) + l * FF * FF;
    const float* bias = (p == 0 ? bq : (p == 1 ? bk : bv));
    __half* dst = (p == 0 ? g_q : (p == 1 ? g_k : g_v));

    int row0 = blockIdx.x * 128;
    int tid = threadIdx.x;
    int wid = tid >> 5, lane = tid & 31;
    int wm = wid & 3, wn = wid >> 2;
    int kq = tid & 7, rr = tid >> 3;
    int kk = tid & 31, ng = tid >> 5;

    const float* arow[4];
#pragma unroll
    for (int i = 0; i < 4; i++) {
        int rg = row0 + rr + i * 32;
        int node = rg / cnt, mi = rg - node * cnt;
        arow[i] = X + ((size_t)node * ND + (m0 + mi)) * FF;
    }

    float acc[2][8][4];
#pragma unroll
    for (int mt = 0; mt < 2; mt++)
#pragma unroll
        for (int nt = 0; nt < 8; nt++)
#pragma unroll
            for (int e = 0; e < 4; e++) acc[mt][nt][e] = 0.0f;

    int at_r = (lane & 7) + ((lane >> 3) & 1) * 8;
    int at_k = (lane >> 4) * 8;
    int bt_n = (lane & 7) + ((lane & 16) ? 8 : 0);
    int bt_k = ((lane >> 3) & 1) * 8;

    auto stage = [&](int c, int st) {
        int f0 = c * 32;
        __half* Ah = smh + st * 2 * SARR;
#pragma unroll
        for (int i = 0; i < 4; i++) {
            int r = rr + i * 32;
            float4 v = *(const float4*)(arow[i] + f0 + kq * 4);
            union { __half2 h2[2]; uint2 u; } pk;
            pk.h2[0] = __floats2half2_rn(v.x, v.y);
            pk.h2[1] = __floats2half2_rn(v.z, v.w);
            *(uint2*)(Ah + r * SPITCH + kq * 4) = pk.u;
        }
        __half* Bh = Ah + SARR;
#pragma unroll
        for (int j = 0; j < 4; j++) {
            int n0 = ng * 16 + j * 4;
            float4 w = *(const float4*)(W + (size_t)(f0 + kk) * 128 + n0);
            float ws[4] = {w.x, w.y, w.z, w.w};
#pragma unroll
            for (int e = 0; e < 4; e++)
                Bh[(n0 + e) * SPITCH + kk] = __float2half_rn(ws[e]);
        }
    };

    stage(0, 0);
    __syncthreads();
    for (int c = 0; c < 4; c++) {
        int st = c & 1;
        if (c + 1 < 4) stage(c + 1, st ^ 1);
        mma_chunk_h<SPITCH, 2>(smh + st * 2 * SARR, acc, wm, wn, at_r, at_k, bt_n, bt_k);
        __syncthreads();
    }

    int tr = lane >> 2, tc = (lane & 3) * 2;
#pragma unroll
    for (int mt = 0; mt < 2; mt++) {
#pragma unroll
        for (int half = 0; half < 2; half++) {
            int rgl = row0 + wm * 32 + mt * 16 + tr + half * 8;
            int node = rgl / cnt, mi = rgl - node * cnt;
            size_t obase = (size_t)node * MCH + (m0 + mi) * FF;
#pragma unroll
            for (int nt = 0; nt < 8; nt++) {
                int col = wn * 64 + nt * 8 + tc;
                float d0 = acc[mt][nt][half * 2 + 0];
                float d1 = acc[mt][nt][half * 2 + 1];
                if (l == 0) { d0 += bias[col]; d1 += bias[col + 1]; }
                *(__half2*)(dst + obase + col) = __floats2half2_rn(d0, d1);
            }
        }
    }
}

// ---------------- kernel: score partials, software-pipelined fp16 mma ---------
// Per iteration: cvtsts(c+1) consumes raws loaded last iteration; loadraw(c+2)
// issues LDGs whose latency is covered by mma(c); then mma(c).
#define KP2 72
#define KA2 (128 * KP2)
#define KS_SMEM (2 * 2 * KA2 * 2)   // 73728 B

__global__ void __launch_bounds__(256, 2)
k_score() {
    extern __shared__ unsigned char smraw[];
    __half* smh = (__half*)smraw;

    int zz = blockIdx.z;
    int b = zz / 9, sp = zz - b * 9;
    int a = sp / 3, mc = sp - a * 3;
    int nb_i = b * NB + blockIdx.x * 128;
    int nb_j = b * NB + blockIdx.y * 128;
    int tid = threadIdx.x;
    int wid = tid >> 5, lane = tid & 31;
    int wm = wid & 3, wn = wid >> 2;
    int kq = tid & 7, rr = tid >> 3;
    int chbase = mc * 384;

    float acc[2][8][4];
#pragma unroll
    for (int mt = 0; mt < 2; mt++)
#pragma unroll
        for (int nt = 0; nt < 8; nt++)
#pragma unroll
            for (int e = 0; e < 4; e++) acc[mt][nt][e] = 0.0f;

    int at_r = (lane & 7) + ((lane >> 3) & 1) * 8;
    int at_k = (lane >> 4) * 8;
    int bt_n = (lane & 7) + ((lane & 16) ? 8 : 0);
    int bt_k = ((lane >> 3) & 1) * 8;

    uint2 raw[8];

    auto loadraw = [&](int c) {
        int ch = chbase + c * 32 + kq * 4;
#pragma unroll
        for (int pass = 0; pass < 2; pass++) {
            const __half* src = pass == 0 ? g_q : g_k;
            int nb = pass == 0 ? nb_i : nb_j;
#pragma unroll
            for (int i = 0; i < 4; i++) {
                int node = nb + rr + i * 32;
                raw[pass * 4 + i] = *(const uint2*)(src + (size_t)node * MCH + ch);
            }
        }
    };

    auto cvtsts = [&](int c, int st) {
        int chl = c * 32 + kq * 4;
        int f   = (chl & 127) >> 1;
#pragma unroll
        for (int pass = 0; pass < 2; pass++) {
            int nb = pass == 0 ? nb_i : nb_j;
            __half* D = smh + st * 2 * KA2 + pass * KA2;
#pragma unroll
            for (int i = 0; i < 4; i++) {
                int r = rr + i * 32;
                int node = nb + r;
                const float* tc = g_cos + node * 192 + a * 64 + f;
                const float* ts = g_sin + node * 192 + a * 64 + f;
                float c0 = tc[0], c1 = tc[1];
                float s0 = ts[0], s1 = ts[1];
                union { __half2 h2[2]; uint2 u; } rw;
                rw.u = raw[pass * 4 + i];
                float2 v01 = __half22float2(rw.h2[0]);
                float2 v23 = __half22float2(rw.h2[1]);
                union { __half2 h2[2]; uint2 u; } p;
                p.h2[0] = __floats2half2_rn(v01.x * c0, v01.y * c0);
                p.h2[1] = __floats2half2_rn(v23.x * c1, v23.y * c1);
                *(uint2*)(D + r * KP2 + kq * 4) = p.u;
                p.h2[0] = __floats2half2_rn(v01.x * s0, v01.y * s0);
                p.h2[1] = __floats2half2_rn(v23.x * s1, v23.y * s1);
                *(uint2*)(D + r * KP2 + 32 + kq * 4) = p.u;
            }
        }
    };

    loadraw(0);
    cvtsts(0, 0);
    loadraw(1);
    __syncthreads();
    for (int c = 0; c < 12; c++) {
        int st = c & 1;
        if (c + 1 < 12) cvtsts(c + 1, st ^ 1);
        if (c + 2 < 12) loadraw(c + 2);
        mma_chunk_h<KP2, 4>(smh + st * 2 * KA2, acc, wm, wn, at_r, at_k, bt_n, bt_k);
        __syncthreads();
    }

    size_t base = ((size_t)sp * BB + b) * (NB * NB);
    int gr = blockIdx.x * 128 + wm * 32;
    int gc = blockIdx.y * 128 + wn * 64;
    int tr = lane >> 2, tc2 = (lane & 3) * 2;
#pragma unroll
    for (int mt = 0; mt < 2; mt++) {
#pragma unroll
        for (int nt = 0; nt < 8; nt++) {
            int r0 = gr + mt * 16 + tr;
            int cc = gc + nt * 8 + tc2;
            float2 d01 = make_float2(acc[mt][nt][0], acc[mt][nt][1]);
            float2 d23 = make_float2(acc[mt][nt][2], acc[mt][nt][3]);
            *(float2*)(g_Spart + base + (size_t)r0 * NB + cc) = d01;
            *(float2*)(g_Spart + base + (size_t)(r0 + 8) * NB + cc) = d23;
        }
    }
}

// ---------------- kernel: slab reduce (float4) ---------------------------------
__global__ void k_reduceS() {
    int i = (blockIdx.x * 256 + threadIdx.x) * 4;
    if (i >= SZSLAB) return;
    float4 s = *(const float4*)(g_Spart + i);
#pragma unroll
    for (int sl = 1; sl < 9; sl++) {
        float4 t = *(const float4*)(g_Spart + (size_t)sl * SZSLAB + i);
        s.x += t.x; s.y += t.y; s.z += t.z; s.w += t.w;
    }
    s.x *= (1.0f / 3.0f); s.y *= (1.0f / 3.0f);
    s.z *= (1.0f / 3.0f); s.w *= (1.0f / 3.0f);
    *(float4*)(g_S + i) = s;
}

// ---------------- kernel: out = Sbar @ V (+mask) via fp16 mma.sync -------------
__global__ void __launch_bounds__(256, 2)
k_out(const int* __restrict__ bseg, const int* __restrict__ gmask,
      float* __restrict__ out) {
    extern __shared__ unsigned char smraw[];
    __half* smh = (__half*)smraw;

    int b = blockIdx.z;
    int r0 = blockIdx.x * 128;
    int d0 = blockIdx.y * 128;
    int tid = threadIdx.x;
    int wid = tid >> 5, lane = tid & 31;
    int wm = wid & 3, wn = wid >> 2;
    int kq = tid & 7, rr = tid >> 3;
    int kk = tid & 31, ng = tid >> 5;

    float acc[2][8][4];
#pragma unroll
    for (int mt = 0; mt < 2; mt++)
#pragma unroll
        for (int nt = 0; nt < 8; nt++)
#pragma unroll
            for (int e = 0; e < 4; e++) acc[mt][nt][e] = 0.0f;

    int at_r = (lane & 7) + ((lane >> 3) & 1) * 8;
    int at_k = (lane >> 4) * 8;
    int bt_n = (lane & 7) + ((lane & 16) ? 8 : 0);
    int bt_k = ((lane >> 3) & 1) * 8;

    auto stage = [&](int c, int st) {
        int j0 = c * 32;
        __half* Ah = smh + st * 2 * SARR;
#pragma unroll
        for (int i = 0; i < 4; i++) {
            int r = rr + i * 32;
            float4 v = *(const float4*)(g_S + ((size_t)b * NB + r0 + r) * NB + j0 + kq * 4);
            union { __half2 h2[2]; uint2 u; } pk;
            pk.h2[0] = __floats2half2_rn(v.x, v.y);
            pk.h2[1] = __floats2half2_rn(v.z, v.w);
            *(uint2*)(Ah + r * SPITCH + kq * 4) = pk.u;
        }
        __half* Bh = Ah + SARR;
#pragma unroll
        for (int j = 0; j < 4; j++) {
            int n0 = ng * 16 + j * 4;
            union { __half h[4]; uint2 u; } rawv;
            rawv.u = *(const uint2*)(g_v + ((size_t)(b * NB + j0 + kk)) * MCH + d0 + n0);
#pragma unroll
            for (int e = 0; e < 4; e++)
                Bh[(n0 + e) * SPITCH + kk] = rawv.h[e];
        }
    };

    stage(0, 0);
    __syncthreads();
    for (int c = 0; c < 8; c++) {
        int st = c & 1;
        if (c + 1 < 8) stage(c + 1, st ^ 1);
        mma_chunk_h<SPITCH, 2>(smh + st * 2 * SARR, acc, wm, wn, at_r, at_k, bt_n, bt_k);
        __syncthreads();
    }

    int tr = lane >> 2, tc = (lane & 3) * 2;
#pragma unroll
    for (int mt = 0; mt < 2; mt++) {
#pragma unroll
        for (int half = 0; half < 2; half++) {
            int node = b * NB + r0 + wm * 32 + mt * 16 + tr + half * 8;
            bool mk = gmask[bseg[node]] != 0;
#pragma unroll
            for (int nt = 0; nt < 8; nt++) {
                int col = wn * 64 + nt * 8 + tc;
                float o0 = mk ? acc[mt][nt][half * 2 + 0] : 0.0f;
                float o1 = mk ? acc[mt][nt][half * 2 + 1] : 0.0f;
                *(float2*)(out + (size_t)node * MCH + d0 + col) = make_float2(o0, o1);
            }
        }
    }
}

// ---------------- launcher ----------------------------------------------------
extern "C" void kernel_launch(void* const* d_in, const int* in_sizes, int n_in,
                              void* d_out, int out_size) {
    const float* X   = (const float*)d_in[0];
    const float* pos = (const float*)d_in[1];
    const int* bseg  = (const int*)d_in[2];
    const int* gmask = (const int*)d_in[3];   // bool -> int32 in harness
    const float* Wq = (const float*)d_in[4];
    const float* bq = (const float*)d_in[5];
    const float* Wk = (const float*)d_in[6];
    const float* bk = (const float*)d_in[7];
    const float* Wv = (const float*)d_in[8];
    const float* bv = (const float*)d_in[9];
    float* out = (float*)d_out;

    cudaFuncSetAttribute(k_proj,  cudaFuncAttributeMaxDynamicSharedMemorySize, PO_SMEM);
    cudaFuncSetAttribute(k_score, cudaFuncAttributeMaxDynamicSharedMemorySize, KS_SMEM);
    cudaFuncSetAttribute(k_out,   cudaFuncAttributeMaxDynamicSharedMemorySize, PO_SMEM);

    k_cs<<<(NN * 3 * NFREQ + 255) / 256, 256>>>(pos);
    k_proj<<<dim3(160, 1, 9), 256, PO_SMEM>>>(X, Wq, bq, Wk, bk, Wv, bv);
    k_score<<<dim3(2, 2, BB * 9), 256, KS_SMEM>>>();
    k_reduceS<<<SZSLAB / 1024, 256>>>();
    k_out<<<dim3(2, 9, BB), 256, PO_SMEM>>>(bseg, gmask, out);
}

// round 14
// speedup vs baseline: 1.3689x; 1.1388x over previous
#include <cuda_runtime.h>
#include <cuda_fp16.h>
#include <cstdint>

#define NN   4096
#define BB   16
#define NB   256      // nodes per batch
#define ND   9        // NUM_DEG
#define FF   128
#define MCH  1152     // 9*128
#define NFREQ 64
#define SZSLAB (BB * NB * NB)

// ---------------- scratch (static device memory; no allocations) ------------
__device__ __half g_q[NN * MCH];
__device__ __half g_k[NN * MCH];
__device__ __half g_v[NN * MCH];
__device__ float g_cs[NN * 3 * NFREQ * 2];   // [node][axis][f]{cos,sin}
__device__ __half g_Spart[9u * SZSLAB];      // 9 partial slabs (fp16)
__device__ __half g_S[SZSLAB];               // reduced S (fp16)

// ---------------- helpers ------------------------------------------------------
__device__ __forceinline__ uint32_t cvsm(const void* p) {
    return (uint32_t)__cvta_generic_to_shared(p);
}
__device__ __forceinline__ void ldsm4(uint32_t* r, uint32_t addr) {
    asm volatile("ldmatrix.sync.aligned.m8n8.x4.shared.b16 {%0,%1,%2,%3}, [%4];"
                 : "=r"(r[0]), "=r"(r[1]), "=r"(r[2]), "=r"(r[3])
                 : "r"(addr));
}
__device__ __forceinline__ void mma16816h(float* d, const uint32_t* a,
                                          uint32_t b0, uint32_t b1) {
    asm volatile(
        "mma.sync.aligned.m16n8k16.row.col.f32.f16.f16.f32 "
        "{%0,%1,%2,%3}, {%4,%5,%6,%7}, {%8,%9}, {%0,%1,%2,%3};"
        : "+f"(d[0]), "+f"(d[1]), "+f"(d[2]), "+f"(d[3])
        : "r"(a[0]), "r"(a[1]), "r"(a[2]), "r"(a[3]), "r"(b0), "r"(b1));
}

// ---- fp16 single-term mma over staged chunk: A at base, B at base+ARR ----
template <int PITCH, int NK16>
__device__ __forceinline__ void mma_chunk_h(
    const __half* base, float acc[2][8][4],
    int wm, int wn, int at_r, int at_k, int bt_n, int bt_k) {
    const int ARR = 128 * PITCH;
    const __half* A = base;
    const __half* B = base + ARR;
#pragma unroll
    for (int k16 = 0; k16 < NK16; k16++) {
        int kc = k16 * 16 + at_k;
        uint32_t ah[2][4];
#pragma unroll
        for (int mt = 0; mt < 2; mt++) {
            int row = wm * 32 + mt * 16 + at_r;
            ldsm4(ah[mt], cvsm(A + row * PITCH + kc));
        }
        int kcb = k16 * 16 + bt_k;
#pragma unroll
        for (int np = 0; np < 4; np++) {
            int n = wn * 64 + np * 16 + bt_n;
            uint32_t bb[4];
            ldsm4(bb, cvsm(B + n * PITCH + kcb));
#pragma unroll
            for (int mt = 0; mt < 2; mt++) {
#pragma unroll
                for (int nt = 0; nt < 2; nt++) {
                    mma16816h(acc[mt][np * 2 + nt], ah[mt],
                              bb[nt * 2], bb[nt * 2 + 1]);
                }
            }
        }
    }
}

#define SPITCH 40
#define SARR   (128 * SPITCH)
#define PO_SMEM (2 * 2 * SARR * 2)   // 40960 B

// ---------------- kernel: interleaved cos/sin table ---------------------------
__global__ void k_cs(const float* __restrict__ pos) {
    int idx = blockIdx.x * 256 + threadIdx.x;
    if (idx >= NN * 3 * NFREQ) return;
    int c = idx & 63;
    int a = (idx >> 6) % 3;
    int n = idx / 192;
    float theta = (8.0f / (63.0f * 10.0f)) * (float)c;
    float ph = pos[n * 3 + a] * theta;
    float s, co;
    sincosf(ph, &s, &co);
    g_cs[idx * 2 + 0] = co;
    g_cs[idx * 2 + 1] = s;
}

// ---------------- kernel: q/k/v projections via fp16 mma.sync ------------------
__global__ void __launch_bounds__(256, 2)
k_proj(const float* __restrict__ X,
       const float* __restrict__ Wq, const float* __restrict__ bq,
       const float* __restrict__ Wk, const float* __restrict__ bk,
       const float* __restrict__ Wv, const float* __restrict__ bv) {
    extern __shared__ unsigned char smraw[];
    __half* smh = (__half*)smraw;

    int z = blockIdx.z;
    int p = z / 3, l = z % 3;
    const int cnt = (l == 0) ? 1 : (l == 1 ? 3 : 5);
    const int m0  = (l == 0) ? 0 : (l == 1 ? 1 : 4);
    int ntiles = (NN * cnt) >> 7;
    if ((int)blockIdx.x >= ntiles) return;

    const float* W    = (p == 0 ? Wq : (p == 1 ? Wk : Wv)) + l * FF * FF;
    const float* bias = (p == 0 ? bq : (p == 1 ? bk : bv));
    __half* dst = (p == 0 ? g_q : (p == 1 ? g_k : g_v));

    int row0 = blockIdx.x * 128;
    int tid = threadIdx.x;
    int wid = tid >> 5, lane = tid & 31;
    int wm = wid & 3, wn = wid >> 2;
    int kq = tid & 7, rr = tid >> 3;
    int kk = tid & 31, ng = tid >> 5;

    const float* arow[4];
#pragma unroll
    for (int i = 0; i < 4; i++) {
        int rg = row0 + rr + i * 32;
        int node = rg / cnt, mi = rg - node * cnt;
        arow[i] = X + ((size_t)node * ND + (m0 + mi)) * FF;
    }

    float acc[2][8][4];
#pragma unroll
    for (int mt = 0; mt < 2; mt++)
#pragma unroll
        for (int nt = 0; nt < 8; nt++)
#pragma unroll
            for (int e = 0; e < 4; e++) acc[mt][nt][e] = 0.0f;

    int at_r = (lane & 7) + ((lane >> 3) & 1) * 8;
    int at_k = (lane >> 4) * 8;
    int bt_n = (lane & 7) + ((lane & 16) ? 8 : 0);
    int bt_k = ((lane >> 3) & 1) * 8;

    auto stage = [&](int c, int st) {
        int f0 = c * 32;
        __half* Ah = smh + st * 2 * SARR;
#pragma unroll
        for (int i = 0; i < 4; i++) {
            int r = rr + i * 32;
            float4 v = *(const float4*)(arow[i] + f0 + kq * 4);
            union { __half2 h2[2]; uint2 u; } pk;
            pk.h2[0] = __floats2half2_rn(v.x, v.y);
            pk.h2[1] = __floats2half2_rn(v.z, v.w);
            *(uint2*)(Ah + r * SPITCH + kq * 4) = pk.u;
        }
        __half* Bh = Ah + SARR;
#pragma unroll
        for (int j = 0; j < 4; j++) {
            int n0 = ng * 16 + j * 4;
            float4 w = *(const float4*)(W + (size_t)(f0 + kk) * 128 + n0);
            float ws[4] = {w.x, w.y, w.z, w.w};
#pragma unroll
            for (int e = 0; e < 4; e++)
                Bh[(n0 + e) * SPITCH + kk] = __float2half_rn(ws[e]);
        }
    };

    stage(0, 0);
    __syncthreads();
    for (int c = 0; c < 4; c++) {
        int st = c & 1;
        if (c + 1 < 4) stage(c + 1, st ^ 1);
        mma_chunk_h<SPITCH, 2>(smh + st * 2 * SARR, acc, wm, wn, at_r, at_k, bt_n, bt_k);
        __syncthreads();
    }

    int tr = lane >> 2, tc = (lane & 3) * 2;
#pragma unroll
    for (int mt = 0; mt < 2; mt++) {
#pragma unroll
        for (int half = 0; half < 2; half++) {
            int rgl = row0 + wm * 32 + mt * 16 + tr + half * 8;
            int node = rgl / cnt, mi = rgl - node * cnt;
            size_t obase = (size_t)node * MCH + (m0 + mi) * FF;
#pragma unroll
            for (int nt = 0; nt < 8; nt++) {
                int col = wn * 64 + nt * 8 + tc;
                float d0 = acc[mt][nt][half * 2 + 0];
                float d1 = acc[mt][nt][half * 2 + 1];
                if (l == 0) { d0 += bias[col]; d1 += bias[col + 1]; }
                *(__half2*)(dst + obase + col) = __floats2half2_rn(d0, d1);
            }
        }
    }
}

// ---------------- kernel: score partials, software-pipelined fp16 mma ---------
#define KP2 72
#define KA2 (128 * KP2)
#define KS_SMEM (2 * 2 * KA2 * 2)   // 73728 B

__global__ void __launch_bounds__(256, 2)
k_score() {
    extern __shared__ unsigned char smraw[];
    __half* smh = (__half*)smraw;

    int zz = blockIdx.z;
    int b = zz / 9, sp = zz - b * 9;
    int a = sp / 3, mc = sp - a * 3;
    int nb_i = b * NB + blockIdx.x * 128;
    int nb_j = b * NB + blockIdx.y * 128;
    int tid = threadIdx.x;
    int wid = tid >> 5, lane = tid & 31;
    int wm = wid & 3, wn = wid >> 2;
    int kq = tid & 7, rr = tid >> 3;
    int chbase = mc * 384;

    float acc[2][8][4];
#pragma unroll
    for (int mt = 0; mt < 2; mt++)
#pragma unroll
        for (int nt = 0; nt < 8; nt++)
#pragma unroll
            for (int e = 0; e < 4; e++) acc[mt][nt][e] = 0.0f;

    int at_r = (lane & 7) + ((lane >> 3) & 1) * 8;
    int at_k = (lane >> 4) * 8;
    int bt_n = (lane & 7) + ((lane & 16) ? 8 : 0);
    int bt_k = ((lane >> 3) & 1) * 8;

    uint2 raw[8];

    auto loadraw = [&](int c) {
        int ch = chbase + c * 32 + kq * 4;
#pragma unroll
        for (int pass = 0; pass < 2; pass++) {
            const __half* src = pass == 0 ? g_q : g_k;
            int nb = pass == 0 ? nb_i : nb_j;
#pragma unroll
            for (int i = 0; i < 4; i++) {
                int node = nb + rr + i * 32;
                raw[pass * 4 + i] = *(const uint2*)(src + (size_t)node * MCH + ch);
            }
        }
    };

    auto cvtsts = [&](int c, int st) {
        int chl = c * 32 + kq * 4;
        int f   = (chl & 127) >> 1;   // even
#pragma unroll
        for (int pass = 0; pass < 2; pass++) {
            int nb = pass == 0 ? nb_i : nb_j;
            __half* D = smh + st * 2 * KA2 + pass * KA2;
#pragma unroll
            for (int i = 0; i < 4; i++) {
                int r = rr + i * 32;
                int node = nb + r;
                // interleaved table: (cos f, sin f, cos f+1, sin f+1)
                float4 cs = *(const float4*)(g_cs + ((size_t)(node * 3 + a) * 64 + f) * 2);
                float c0 = cs.x, s0 = cs.y, c1 = cs.z, s1 = cs.w;
                union { __half2 h2[2]; uint2 u; } rw;
                rw.u = raw[pass * 4 + i];
                float2 v01 = __half22float2(rw.h2[0]);
                float2 v23 = __half22float2(rw.h2[1]);
                union { __half2 h2[2]; uint2 u; } p;
                p.h2[0] = __floats2half2_rn(v01.x * c0, v01.y * c0);
                p.h2[1] = __floats2half2_rn(v23.x * c1, v23.y * c1);
                *(uint2*)(D + r * KP2 + kq * 4) = p.u;
                p.h2[0] = __floats2half2_rn(v01.x * s0, v01.y * s0);
                p.h2[1] = __floats2half2_rn(v23.x * s1, v23.y * s1);
                *(uint2*)(D + r * KP2 + 32 + kq * 4) = p.u;
            }
        }
    };

    loadraw(0);
    cvtsts(0, 0);
    loadraw(1);
    __syncthreads();
    for (int c = 0; c < 12; c++) {
        int st = c & 1;
        if (c + 1 < 12) cvtsts(c + 1, st ^ 1);
        if (c + 2 < 12) loadraw(c + 2);
        mma_chunk_h<KP2, 4>(smh + st * 2 * KA2, acc, wm, wn, at_r, at_k, bt_n, bt_k);
        __syncthreads();
    }

    // epilogue -> fp16 partial slab
    size_t base = ((size_t)sp * BB + b) * (NB * NB);
    int gr = blockIdx.x * 128 + wm * 32;
    int gc = blockIdx.y * 128 + wn * 64;
    int tr = lane >> 2, tc2 = (lane & 3) * 2;
#pragma unroll
    for (int mt = 0; mt < 2; mt++) {
#pragma unroll
        for (int nt = 0; nt < 8; nt++) {
            int r0 = gr + mt * 16 + tr;
            int cc = gc + nt * 8 + tc2;
            *(__half2*)(g_Spart + base + (size_t)r0 * NB + cc) =
                __floats2half2_rn(acc[mt][nt][0], acc[mt][nt][1]);
            *(__half2*)(g_Spart + base + (size_t)(r0 + 8) * NB + cc) =
                __floats2half2_rn(acc[mt][nt][2], acc[mt][nt][3]);
        }
    }
}

// ---------------- kernel: slab reduce (fp16 in, fp32 sum, fp16 out) -----------
__global__ void k_reduceS() {
    int i = (blockIdx.x * 256 + threadIdx.x) * 8;
    if (i >= SZSLAB) return;
    float s[8];
#pragma unroll
    for (int e = 0; e < 8; e++) s[e] = 0.0f;
#pragma unroll
    for (int sl = 0; sl < 9; sl++) {
        union { __half2 h2[4]; uint4 u; } t;
        t.u = *(const uint4*)(g_Spart + (size_t)sl * SZSLAB + i);
#pragma unroll
        for (int e = 0; e < 4; e++) {
            float2 v = __half22float2(t.h2[e]);
            s[e * 2 + 0] += v.x;
            s[e * 2 + 1] += v.y;
        }
    }
    union { __half2 h2[4]; uint4 u; } o;
#pragma unroll
    for (int e = 0; e < 4; e++)
        o.h2[e] = __floats2half2_rn(s[e * 2] * (1.0f / 3.0f),
                                    s[e * 2 + 1] * (1.0f / 3.0f));
    *(uint4*)(g_S + i) = o.u;
}

// ---------------- kernel: out = Sbar @ V (+mask) via fp16 mma.sync -------------
__global__ void __launch_bounds__(256, 2)
k_out(const int* __restrict__ bseg, const int* __restrict__ gmask,
      float* __restrict__ out) {
    extern __shared__ unsigned char smraw[];
    __half* smh = (__half*)smraw;

    int b = blockIdx.z;
    int r0 = blockIdx.x * 128;
    int d0 = blockIdx.y * 128;
    int tid = threadIdx.x;
    int wid = tid >> 5, lane = tid & 31;
    int wm = wid & 3, wn = wid >> 2;
    int kq = tid & 7, rr = tid >> 3;
    int kk = tid & 31, ng = tid >> 5;

    float acc[2][8][4];
#pragma unroll
    for (int mt = 0; mt < 2; mt++)
#pragma unroll
        for (int nt = 0; nt < 8; nt++)
#pragma unroll
            for (int e = 0; e < 4; e++) acc[mt][nt][e] = 0.0f;

    int at_r = (lane & 7) + ((lane >> 3) & 1) * 8;
    int at_k = (lane >> 4) * 8;
    int bt_n = (lane & 7) + ((lane & 16) ? 8 : 0);
    int bt_k = ((lane >> 3) & 1) * 8;

    auto stage = [&](int c, int st) {
        int j0 = c * 32;
        __half* Ah = smh + st * 2 * SARR;
#pragma unroll
        for (int i = 0; i < 4; i++) {
            int r = rr + i * 32;
            *(uint2*)(Ah + r * SPITCH + kq * 4) =
                *(const uint2*)(g_S + ((size_t)b * NB + r0 + r) * NB + j0 + kq * 4);
        }
        __half* Bh = Ah + SARR;
#pragma unroll
        for (int j = 0; j < 4; j++) {
            int n0 = ng * 16 + j * 4;
            union { __half h[4]; uint2 u; } rawv;
            rawv.u = *(const uint2*)(g_v + ((size_t)(b * NB + j0 + kk)) * MCH + d0 + n0);
#pragma unroll
            for (int e = 0; e < 4; e++)
                Bh[(n0 + e) * SPITCH + kk] = rawv.h[e];
        }
    };

    stage(0, 0);
    __syncthreads();
    for (int c = 0; c < 8; c++) {
        int st = c & 1;
        if (c + 1 < 8) stage(c + 1, st ^ 1);
        mma_chunk_h<SPITCH, 2>(smh + st * 2 * SARR, acc, wm, wn, at_r, at_k, bt_n, bt_k);
        __syncthreads();
    }

    int tr = lane >> 2, tc = (lane & 3) * 2;
#pragma unroll
    for (int mt = 0; mt < 2; mt++) {
#pragma unroll
        for (int half = 0; half < 2; half++) {
            int node = b * NB + r0 + wm * 32 + mt * 16 + tr + half * 8;
            bool mk = gmask[bseg[node]] != 0;
#pragma unroll
            for (int nt = 0; nt < 8; nt++) {
                int col = wn * 64 + nt * 8 + tc;
                float o0 = mk ? acc[mt][nt][half * 2 + 0] : 0.0f;
                float o1 = mk ? acc[mt][nt][half * 2 + 1] : 0.0f;
                *(float2*)(out + (size_t)node * MCH + d0 + col) = make_float2(o0, o1);
            }
        }
    }
}

// ---------------- launcher ----------------------------------------------------
extern "C" void kernel_launch(void* const* d_in, const int* in_sizes, int n_in,
                              void* d_out, int out_size) {
    const float* X   = (const float*)d_in[0];
    const float* pos = (const float*)d_in[1];
    const int* bseg  = (const int*)d_in[2];
    const int* gmask = (const int*)d_in[3];   // bool -> int32 in harness
    const float* Wq = (const float*)d_in[4];
    const float* bq = (const float*)d_in[5];
    const float* Wk = (const float*)d_in[6];
    const float* bk = (const float*)d_in[7];
    const float* Wv = (const float*)d_in[8];
    const float* bv = (const float*)d_in[9];
    float* out = (float*)d_out;

    cudaFuncSetAttribute(k_proj,  cudaFuncAttributeMaxDynamicSharedMemorySize, PO_SMEM);
    cudaFuncSetAttribute(k_score, cudaFuncAttributeMaxDynamicSharedMemorySize, KS_SMEM);
    cudaFuncSetAttribute(k_out,   cudaFuncAttributeMaxDynamicSharedMemorySize, PO_SMEM);

    k_cs<<<(NN * 3 * NFREQ + 255) / 256, 256>>>(pos);
    k_proj<<<dim3(160, 1, 9), 256, PO_SMEM>>>(X, Wq, bq, Wk, bk, Wv, bv);
    k_score<<<dim3(2, 2, BB * 9), 256, KS_SMEM>>>();
    k_reduceS<<<SZSLAB / 2048, 256>>>();
    k_out<<<dim3(2, 9, BB), 256, PO_SMEM>>>(bseg, gmask, out);
}

// round 15
// speedup vs baseline: 1.4407x; 1.0524x over previous
#include <cuda_runtime.h>
#include <cuda_fp16.h>
#include <cstdint>

#define NN   4096
#define BB   16
#define NB   256      // nodes per batch
#define ND   9        // NUM_DEG
#define FF   128
#define MCH  1152     // 9*128
#define NFREQ 64
#define SZSLAB (BB * NB * NB)

// ---------------- scratch (static device memory; no allocations) ------------
__device__ __half g_q[NN * MCH];
__device__ __half g_k[NN * MCH];
__device__ __half g_v[NN * MCH];
__device__ __half g_csh[NN * 3 * 32 * 8];   // [node][axis][fpair]{c0c0c1c1 s0s0s1s1}
__device__ __half g_wt[9 * FF * FF];        // W transposed: [z][n][k] fp16
__device__ __half g_Spart[9u * SZSLAB];     // 9 partial slabs (fp16)
__device__ __half g_S[SZSLAB];              // reduced S (fp16)

// ---------------- helpers ------------------------------------------------------
__device__ __forceinline__ uint32_t cvsm(const void* p) {
    return (uint32_t)__cvta_generic_to_shared(p);
}
__device__ __forceinline__ void ldsm4(uint32_t* r, uint32_t addr) {
    asm volatile("ldmatrix.sync.aligned.m8n8.x4.shared.b16 {%0,%1,%2,%3}, [%4];"
                 : "=r"(r[0]), "=r"(r[1]), "=r"(r[2]), "=r"(r[3])
                 : "r"(addr));
}
__device__ __forceinline__ void mma16816h(float* d, const uint32_t* a,
                                          uint32_t b0, uint32_t b1) {
    asm volatile(
        "mma.sync.aligned.m16n8k16.row.col.f32.f16.f16.f32 "
        "{%0,%1,%2,%3}, {%4,%5,%6,%7}, {%8,%9}, {%0,%1,%2,%3};"
        : "+f"(d[0]), "+f"(d[1]), "+f"(d[2]), "+f"(d[3])
        : "r"(a[0]), "r"(a[1]), "r"(a[2]), "r"(a[3]), "r"(b0), "r"(b1));
}

// ---- fp16 single-term mma over staged chunk: A at base, B at base+ARR ----
template <int PITCH, int NK16>
__device__ __forceinline__ void mma_chunk_h(
    const __half* base, float acc[2][8][4],
    int wm, int wn, int at_r, int at_k, int bt_n, int bt_k) {
    const int ARR = 128 * PITCH;
    const __half* A = base;
    const __half* B = base + ARR;
#pragma unroll
    for (int k16 = 0; k16 < NK16; k16++) {
        int kc = k16 * 16 + at_k;
        uint32_t ah[2][4];
#pragma unroll
        for (int mt = 0; mt < 2; mt++) {
            int row = wm * 32 + mt * 16 + at_r;
            ldsm4(ah[mt], cvsm(A + row * PITCH + kc));
        }
        int kcb = k16 * 16 + bt_k;
#pragma unroll
        for (int np = 0; np < 4; np++) {
            int n = wn * 64 + np * 16 + bt_n;
            uint32_t bb[4];
            ldsm4(bb, cvsm(B + n * PITCH + kcb));
#pragma unroll
            for (int mt = 0; mt < 2; mt++) {
#pragma unroll
                for (int nt = 0; nt < 2; nt++) {
                    mma16816h(acc[mt][np * 2 + nt], ah[mt],
                              bb[nt * 2], bb[nt * 2 + 1]);
                }
            }
        }
    }
}

#define SPITCH 40
#define SARR   (128 * SPITCH)
#define PO_SMEM (2 * 2 * SARR * 2)   // 40960 B

// ---------------- kernel: packed fp16 cos/sin tables ---------------------------
__global__ void k_cs(const float* __restrict__ pos) {
    int idx = blockIdx.x * 256 + threadIdx.x;   // (n*3+a)*32 + j
    if (idx >= NN * 3 * 32) return;
    int j = idx & 31;
    int a = (idx >> 5) % 3;
    int n = idx / 96;
    float th0 = (8.0f / (63.0f * 10.0f)) * (float)(2 * j);
    float th1 = (8.0f / (63.0f * 10.0f)) * (float)(2 * j + 1);
    float pa = pos[n * 3 + a];
    float s0, c0, s1, c1;
    sincosf(pa * th0, &s0, &c0);
    sincosf(pa * th1, &s1, &c1);
    __half2* e = (__half2*)(g_csh + (size_t)idx * 8);
    e[0] = __floats2half2_rn(c0, c0);
    e[1] = __floats2half2_rn(c1, c1);
    e[2] = __floats2half2_rn(s0, s0);
    e[3] = __floats2half2_rn(s1, s1);
}

// ---------------- kernel: pre-transpose W -> fp16 [z][n][k] --------------------
__global__ void k_prew(const float* __restrict__ Wq,
                       const float* __restrict__ Wk,
                       const float* __restrict__ Wv) {
    int idx = blockIdx.x * 256 + threadIdx.x;   // (z, n, k2)
    if (idx >= 9 * 128 * 64) return;
    int k2 = idx & 63;
    int n  = (idx >> 6) & 127;
    int z  = idx >> 13;
    int p = z / 3, l = z % 3;
    const float* W = (p == 0 ? Wq : (p == 1 ? Wk : Wv)) + l * FF * FF;
    float w0 = W[(2 * k2) * 128 + n];
    float w1 = W[(2 * k2 + 1) * 128 + n];
    *(__half2*)(g_wt + ((size_t)z * 128 + n) * 128 + 2 * k2) =
        __floats2half2_rn(w0, w1);
}

// ---------------- kernel: q/k/v projections via fp16 mma.sync ------------------
__global__ void __launch_bounds__(256, 2)
k_proj(const float* __restrict__ X,
       const float* __restrict__ bq, const float* __restrict__ bk,
       const float* __restrict__ bv) {
    extern __shared__ unsigned char smraw[];
    __half* smh = (__half*)smraw;

    int z = blockIdx.z;
    int p = z / 3, l = z % 3;
    const int cnt = (l == 0) ? 1 : (l == 1 ? 3 : 5);
    const int m0  = (l == 0) ? 0 : (l == 1 ? 1 : 4);
    int ntiles = (NN * cnt) >> 7;
    if ((int)blockIdx.x >= ntiles) return;

    const __half* Wt  = g_wt + (size_t)z * FF * FF;
    const float* bias = (p == 0 ? bq : (p == 1 ? bk : bv));
    __half* dst = (p == 0 ? g_q : (p == 1 ? g_k : g_v));

    int row0 = blockIdx.x * 128;
    int tid = threadIdx.x;
    int wid = tid >> 5, lane = tid & 31;
    int wm = wid & 3, wn = wid >> 2;
    int kq = tid & 7, rr = tid >> 3;
    int brow = tid & 127, bko = (tid >> 7) * 8;

    const float* arow[4];
#pragma unroll
    for (int i = 0; i < 4; i++) {
        int rg = row0 + rr + i * 32;
        int node = rg / cnt, mi = rg - node * cnt;
        arow[i] = X + ((size_t)node * ND + (m0 + mi)) * FF;
    }

    float acc[2][8][4];
#pragma unroll
    for (int mt = 0; mt < 2; mt++)
#pragma unroll
        for (int nt = 0; nt < 8; nt++)
#pragma unroll
            for (int e = 0; e < 4; e++) acc[mt][nt][e] = 0.0f;

    int at_r = (lane & 7) + ((lane >> 3) & 1) * 8;
    int at_k = (lane >> 4) * 8;
    int bt_n = (lane & 7) + ((lane & 16) ? 8 : 0);
    int bt_k = ((lane >> 3) & 1) * 8;

    auto stage = [&](int c, int st) {
        int f0 = c * 32;
        __half* Ah = smh + st * 2 * SARR;
#pragma unroll
        for (int i = 0; i < 4; i++) {
            int r = rr + i * 32;
            float4 v = *(const float4*)(arow[i] + f0 + kq * 4);
            union { __half2 h2[2]; uint2 u; } pk;
            pk.h2[0] = __floats2half2_rn(v.x, v.y);
            pk.h2[1] = __floats2half2_rn(v.z, v.w);
            *(uint2*)(Ah + r * SPITCH + kq * 4) = pk.u;
        }
        __half* Bh = Ah + SARR;
#pragma unroll
        for (int it = 0; it < 2; it++) {
            int ko = bko + it * 16;
            *(uint4*)(Bh + brow * SPITCH + ko) =
                *(const uint4*)(Wt + (size_t)brow * 128 + f0 + ko);
        }
    };

    stage(0, 0);
    __syncthreads();
    for (int c = 0; c < 4; c++) {
        int st = c & 1;
        if (c + 1 < 4) stage(c + 1, st ^ 1);
        mma_chunk_h<SPITCH, 2>(smh + st * 2 * SARR, acc, wm, wn, at_r, at_k, bt_n, bt_k);
        __syncthreads();
    }

    int tr = lane >> 2, tc = (lane & 3) * 2;
#pragma unroll
    for (int mt = 0; mt < 2; mt++) {
#pragma unroll
        for (int half = 0; half < 2; half++) {
            int rgl = row0 + wm * 32 + mt * 16 + tr + half * 8;
            int node = rgl / cnt, mi = rgl - node * cnt;
            size_t obase = (size_t)node * MCH + (m0 + mi) * FF;
#pragma unroll
            for (int nt = 0; nt < 8; nt++) {
                int col = wn * 64 + nt * 8 + tc;
                float d0 = acc[mt][nt][half * 2 + 0];
                float d1 = acc[mt][nt][half * 2 + 1];
                if (l == 0) { d0 += bias[col]; d1 += bias[col + 1]; }
                *(__half2*)(dst + obase + col) = __floats2half2_rn(d0, d1);
            }
        }
    }
}

// ---------------- kernel: score partials, software-pipelined fp16 mma ---------
#define KP2 72
#define KA2 (128 * KP2)
#define KS_SMEM (2 * 2 * KA2 * 2)   // 73728 B

__global__ void __launch_bounds__(256, 2)
k_score() {
    extern __shared__ unsigned char smraw[];
    __half* smh = (__half*)smraw;

    int zz = blockIdx.z;
    int b = zz / 9, sp = zz - b * 9;
    int a = sp / 3, mc = sp - a * 3;
    int nb_i = b * NB + blockIdx.x * 128;
    int nb_j = b * NB + blockIdx.y * 128;
    int tid = threadIdx.x;
    int wid = tid >> 5, lane = tid & 31;
    int wm = wid & 3, wn = wid >> 2;
    int kq = tid & 7, rr = tid >> 3;
    int chbase = mc * 384;

    float acc[2][8][4];
#pragma unroll
    for (int mt = 0; mt < 2; mt++)
#pragma unroll
        for (int nt = 0; nt < 8; nt++)
#pragma unroll
            for (int e = 0; e < 4; e++) acc[mt][nt][e] = 0.0f;

    int at_r = (lane & 7) + ((lane >> 3) & 1) * 8;
    int at_k = (lane >> 4) * 8;
    int bt_n = (lane & 7) + ((lane & 16) ? 8 : 0);
    int bt_k = ((lane >> 3) & 1) * 8;

    uint2 raw[8];

    auto loadraw = [&](int c) {
        int ch = chbase + c * 32 + kq * 4;
#pragma unroll
        for (int pass = 0; pass < 2; pass++) {
            const __half* src = pass == 0 ? g_q : g_k;
            int nb = pass == 0 ? nb_i : nb_j;
#pragma unroll
            for (int i = 0; i < 4; i++) {
                int node = nb + rr + i * 32;
                raw[pass * 4 + i] = *(const uint2*)(src + (size_t)node * MCH + ch);
            }
        }
    };

    auto cvtsts = [&](int c, int st) {
        int chl = c * 32 + kq * 4;
        int j = (chl & 127) >> 2;   // freq-pair index
#pragma unroll
        for (int pass = 0; pass < 2; pass++) {
            int nb = pass == 0 ? nb_i : nb_j;
            __half* D = smh + st * 2 * KA2 + pass * KA2;
#pragma unroll
            for (int i = 0; i < 4; i++) {
                int r = rr + i * 32;
                int node = nb + r;
                union { __half2 h2[4]; uint4 u; } tb;
                tb.u = *(const uint4*)(g_csh + (((size_t)node * 3 + a) * 32 + j) * 8);
                union { __half2 h2[2]; uint2 u; } rw;
                rw.u = raw[pass * 4 + i];
                union { __half2 h2[2]; uint2 u; } o;
                o.h2[0] = __hmul2(rw.h2[0], tb.h2[0]);
                o.h2[1] = __hmul2(rw.h2[1], tb.h2[1]);
                *(uint2*)(D + r * KP2 + kq * 4) = o.u;
                o.h2[0] = __hmul2(rw.h2[0], tb.h2[2]);
                o.h2[1] = __hmul2(rw.h2[1], tb.h2[3]);
                *(uint2*)(D + r * KP2 + 32 + kq * 4) = o.u;
            }
        }
    };

    loadraw(0);
    cvtsts(0, 0);
    loadraw(1);
    __syncthreads();
    for (int c = 0; c < 12; c++) {
        int st = c & 1;
        if (c + 1 < 12) cvtsts(c + 1, st ^ 1);
        if (c + 2 < 12) loadraw(c + 2);
        mma_chunk_h<KP2, 4>(smh + st * 2 * KA2, acc, wm, wn, at_r, at_k, bt_n, bt_k);
        __syncthreads();
    }

    // epilogue -> fp16 partial slab
    size_t base = ((size_t)sp * BB + b) * (NB * NB);
    int gr = blockIdx.x * 128 + wm * 32;
    int gc = blockIdx.y * 128 + wn * 64;
    int tr = lane >> 2, tc2 = (lane & 3) * 2;
#pragma unroll
    for (int mt = 0; mt < 2; mt++) {
#pragma unroll
        for (int nt = 0; nt < 8; nt++) {
            int r0 = gr + mt * 16 + tr;
            int cc = gc + nt * 8 + tc2;
            *(__half2*)(g_Spart + base + (size_t)r0 * NB + cc) =
                __floats2half2_rn(acc[mt][nt][0], acc[mt][nt][1]);
            *(__half2*)(g_Spart + base + (size_t)(r0 + 8) * NB + cc) =
                __floats2half2_rn(acc[mt][nt][2], acc[mt][nt][3]);
        }
    }
}

// ---------------- kernel: slab reduce (fp16 in, fp32 sum, fp16 out) -----------
__global__ void k_reduceS() {
    int i = (blockIdx.x * 256 + threadIdx.x) * 8;
    if (i >= SZSLAB) return;
    float s[8];
#pragma unroll
    for (int e = 0; e < 8; e++) s[e] = 0.0f;
#pragma unroll
    for (int sl = 0; sl < 9; sl++) {
        union { __half2 h2[4]; uint4 u; } t;
        t.u = *(const uint4*)(g_Spart + (size_t)sl * SZSLAB + i);
#pragma unroll
        for (int e = 0; e < 4; e++) {
            float2 v = __half22float2(t.h2[e]);
            s[e * 2 + 0] += v.x;
            s[e * 2 + 1] += v.y;
        }
    }
    union { __half2 h2[4]; uint4 u; } o;
#pragma unroll
    for (int e = 0; e < 4; e++)
        o.h2[e] = __floats2half2_rn(s[e * 2] * (1.0f / 3.0f),
                                    s[e * 2 + 1] * (1.0f / 3.0f));
    *(uint4*)(g_S + i) = o.u;
}

// ---------------- kernel: out = Sbar @ V (+mask) via fp16 mma.sync -------------
__global__ void __launch_bounds__(256, 2)
k_out(const int* __restrict__ bseg, const int* __restrict__ gmask,
      float* __restrict__ out) {
    extern __shared__ unsigned char smraw[];
    __half* smh = (__half*)smraw;

    int b = blockIdx.z;
    int r0 = blockIdx.x * 128;
    int d0 = blockIdx.y * 128;
    int tid = threadIdx.x;
    int wid = tid >> 5, lane = tid & 31;
    int wm = wid & 3, wn = wid >> 2;
    int kq = tid & 7, rr = tid >> 3;
    int kk = tid & 31, ng = tid >> 5;

    float acc[2][8][4];
#pragma unroll
    for (int mt = 0; mt < 2; mt++)
#pragma unroll
        for (int nt = 0; nt < 8; nt++)
#pragma unroll
            for (int e = 0; e < 4; e++) acc[mt][nt][e] = 0.0f;

    int at_r = (lane & 7) + ((lane >> 3) & 1) * 8;
    int at_k = (lane >> 4) * 8;
    int bt_n = (lane & 7) + ((lane & 16) ? 8 : 0);
    int bt_k = ((lane >> 3) & 1) * 8;

    auto stage = [&](int c, int st) {
        int j0 = c * 32;
        __half* Ah = smh + st * 2 * SARR;
#pragma unroll
        for (int i = 0; i < 4; i++) {
            int r = rr + i * 32;
            *(uint2*)(Ah + r * SPITCH + kq * 4) =
                *(const uint2*)(g_S + ((size_t)b * NB + r0 + r) * NB + j0 + kq * 4);
        }
        __half* Bh = Ah + SARR;
#pragma unroll
        for (int j = 0; j < 4; j++) {
            int n0 = ng * 16 + j * 4;
            union { __half h[4]; uint2 u; } rawv;
            rawv.u = *(const uint2*)(g_v + ((size_t)(b * NB + j0 + kk)) * MCH + d0 + n0);
#pragma unroll
            for (int e = 0; e < 4; e++)
                Bh[(n0 + e) * SPITCH + kk] = rawv.h[e];
        }
    };

    stage(0, 0);
    __syncthreads();
    for (int c = 0; c < 8; c++) {
        int st = c & 1;
        if (c + 1 < 8) stage(c + 1, st ^ 1);
        mma_chunk_h<SPITCH, 2>(smh + st * 2 * SARR, acc, wm, wn, at_r, at_k, bt_n, bt_k);
        __syncthreads();
    }

    int tr = lane >> 2, tc = (lane & 3) * 2;
#pragma unroll
    for (int mt = 0; mt < 2; mt++) {
#pragma unroll
        for (int half = 0; half < 2; half++) {
            int node = b * NB + r0 + wm * 32 + mt * 16 + tr + half * 8;
            bool mk = gmask[bseg[node]] != 0;
#pragma unroll
            for (int nt = 0; nt < 8; nt++) {
                int col = wn * 64 + nt * 8 + tc;
                float o0 = mk ? acc[mt][nt][half * 2 + 0] : 0.0f;
                float o1 = mk ? acc[mt][nt][half * 2 + 1] : 0.0f;
                *(float2*)(out + (size_t)node * MCH + d0 + col) = make_float2(o0, o1);
            }
        }
    }
}

// ---------------- launcher ----------------------------------------------------
extern "C" void kernel_launch(void* const* d_in, const int* in_sizes, int n_in,
                              void* d_out, int out_size) {
    const float* X   = (const float*)d_in[0];
    const float* pos = (const float*)d_in[1];
    const int* bseg  = (const int*)d_in[2];
    const int* gmask = (const int*)d_in[3];   // bool -> int32 in harness
    const float* Wq = (const float*)d_in[4];
    const float* bq = (const float*)d_in[5];
    const float* Wk = (const float*)d_in[6];
    const float* bk = (const float*)d_in[7];
    const float* Wv = (const float*)d_in[8];
    const float* bv = (const float*)d_in[9];
    float* out = (float*)d_out;

    cudaFuncSetAttribute(k_proj,  cudaFuncAttributeMaxDynamicSharedMemorySize, PO_SMEM);
    cudaFuncSetAttribute(k_score, cudaFuncAttributeMaxDynamicSharedMemorySize, KS_SMEM);
    cudaFuncSetAttribute(k_out,   cudaFuncAttributeMaxDynamicSharedMemorySize, PO_SMEM);

    k_cs<<<(NN * 3 * 32 + 255) / 256, 256>>>(pos);
    k_prew<<<(9 * 128 * 64 + 255) / 256, 256>>>(Wq, Wk, Wv);
    k_proj<<<dim3(160, 1, 9), 256, PO_SMEM>>>(X, bq, bk, bv);
    k_score<<<dim3(2, 2, BB * 9), 256, KS_SMEM>>>();
    k_reduceS<<<SZSLAB / 2048, 256>>>();
    k_out<<<dim3(2, 9, BB), 256, PO_SMEM>>>(bseg, gmask, out);
}